// round 2
// baseline (speedup 1.0000x reference)
#include <cuda_runtime.h>
#include <cuda_bf16.h>
#include <math.h>

// Problem constants
#define BB    16384
#define HH    32
#define KVH   8
#define DD    128
#define RBIT  128
#define HID   4096      // H*D
#define KOUT  1024      // KVH*D

// Scratch (device globals; no allocations allowed)
__device__ float g_Q[(size_t)BB * HID];   // 256 MB
__device__ float g_K[(size_t)BB * KOUT];  // 64 MB

// ---------------------------------------------------------------------------
// packed f32x2 helpers (ptxas never auto-fuses; see SASS_QUICKREF patterns)
// ---------------------------------------------------------------------------
__device__ __forceinline__ unsigned long long pack2(float x, float y) {
    unsigned long long r;
    asm("mov.b64 %0, {%1,%2};" : "=l"(r) : "f"(x), "f"(y));
    return r;
}
__device__ __forceinline__ void ffma2(unsigned long long& c,
                                      unsigned long long a,
                                      unsigned long long b) {
    asm("fma.rn.f32x2 %0, %1, %2, %0;" : "+l"(c) : "l"(a), "l"(b));
}
__device__ __forceinline__ float2 unpack2(unsigned long long v) {
    float2 r;
    asm("mov.b64 {%0,%1}, %2;" : "=f"(r.x), "=f"(r.y) : "l"(v));
    return r;
}

// ---------------------------------------------------------------------------
// Tiled fp32 GEMM: C[M,N] = A[M,K] @ W[K,N] + bias[N]
// BM=BN=128, BK=16, 256 threads, 8x8 per-thread microtile (as 8x4 f32x2)
// M,N,K all divisible by tile sizes for this problem (16384, 4096/1024, 4096)
// ---------------------------------------------------------------------------
#define BM 128
#define BN 128
#define BK 16

__global__ __launch_bounds__(256) void gemm_bias_kernel(
    const float* __restrict__ A, const float* __restrict__ W,
    const float* __restrict__ bias, float* __restrict__ C,
    int M, int N, int K)
{
    __shared__ float As[BK][BM];
    __shared__ float Ws[BK][BN];

    const int bm = blockIdx.y * BM;
    const int bn = blockIdx.x * BN;
    const int tid = threadIdx.x;
    const int tr = tid >> 4;   // 0..15
    const int tc = tid & 15;   // 0..15

    unsigned long long acc[8][4];
    #pragma unroll
    for (int i = 0; i < 8; i++)
        #pragma unroll
        for (int j = 0; j < 4; j++) acc[i][j] = 0ULL;

    const float* Ab = A + (size_t)bm * K;

    for (int k0 = 0; k0 < K; k0 += BK) {
        // Load A tile (BM x BK) -> As transposed [k][m]
        #pragma unroll
        for (int t = 0; t < 2; t++) {
            int idx = tid + t * 256;          // float4 index, 0..511
            int row = idx >> 2;               // 0..127
            int c4  = idx & 3;                // 0..3
            float4 v = *reinterpret_cast<const float4*>(
                &Ab[(size_t)row * K + k0 + c4 * 4]);
            As[c4 * 4 + 0][row] = v.x;
            As[c4 * 4 + 1][row] = v.y;
            As[c4 * 4 + 2][row] = v.z;
            As[c4 * 4 + 3][row] = v.w;
        }
        // Load W tile (BK x BN) row-major
        #pragma unroll
        for (int t = 0; t < 2; t++) {
            int idx = tid + t * 256;          // float4 index, 0..511
            int row = idx >> 5;               // 0..15
            int c4  = idx & 31;               // 0..31
            *reinterpret_cast<float4*>(&Ws[row][c4 * 4]) =
                *reinterpret_cast<const float4*>(
                    &W[(size_t)(k0 + row) * N + bn + c4 * 4]);
        }
        __syncthreads();

        #pragma unroll
        for (int k = 0; k < BK; k++) {
            float4 a0 = *reinterpret_cast<const float4*>(&As[k][tr * 8]);
            float4 a1 = *reinterpret_cast<const float4*>(&As[k][tr * 8 + 4]);
            float4 b0 = *reinterpret_cast<const float4*>(&Ws[k][tc * 8]);
            float4 b1 = *reinterpret_cast<const float4*>(&Ws[k][tc * 8 + 4]);
            float ra[8] = {a0.x, a0.y, a0.z, a0.w, a1.x, a1.y, a1.z, a1.w};
            unsigned long long rb[4] = {
                pack2(b0.x, b0.y), pack2(b0.z, b0.w),
                pack2(b1.x, b1.y), pack2(b1.z, b1.w)};
            #pragma unroll
            for (int i = 0; i < 8; i++) {
                unsigned long long a2 = pack2(ra[i], ra[i]);
                #pragma unroll
                for (int j = 0; j < 4; j++) ffma2(acc[i][j], a2, rb[j]);
            }
        }
        __syncthreads();
    }

    // Epilogue: + bias, vectorized stores
    const int colb = bn + tc * 8;
    float4 bia0 = *reinterpret_cast<const float4*>(&bias[colb]);
    float4 bia1 = *reinterpret_cast<const float4*>(&bias[colb + 4]);
    #pragma unroll
    for (int i = 0; i < 8; i++) {
        int row = bm + tr * 8 + i;
        float2 c0 = unpack2(acc[i][0]);
        float2 c1 = unpack2(acc[i][1]);
        float2 c2 = unpack2(acc[i][2]);
        float2 c3 = unpack2(acc[i][3]);
        float4 o0 = make_float4(c0.x + bia0.x, c0.y + bia0.y,
                                c1.x + bia0.z, c1.y + bia0.w);
        float4 o1 = make_float4(c2.x + bia1.x, c2.y + bia1.y,
                                c3.x + bia1.z, c3.y + bia1.w);
        *reinterpret_cast<float4*>(&C[(size_t)row * N + colb])     = o0;
        *reinterpret_cast<float4*>(&C[(size_t)row * N + colb + 4]) = o1;
    }
}

// ---------------------------------------------------------------------------
// Fused tail: one block (128 threads) per (b, kvh). Computes k-hash once,
// reuses across the G=4 grouped query heads.
// out[0 : B*H)        = attn_weights
// out[B*H : 2*B*H)    = ham_weights
// ---------------------------------------------------------------------------
__global__ __launch_bounds__(128) void fused_tail_kernel(
    const float* __restrict__ Q, const float* __restrict__ Kp,
    const float* __restrict__ hw, float* __restrict__ out)
{
    const int blk = blockIdx.x;      // b*KVH + kvh
    const int b   = blk >> 3;
    const int kvh = blk & 7;
    const int j   = threadIdx.x;     // 0..127 (dim / rbit index)

    __shared__ float sq[4][128];
    __shared__ float sk[128];
    __shared__ float racc[13][4];

    const float kv = Kp[(size_t)b * KOUT + kvh * DD + j];
    sk[j] = kv;
    float qv[4];
    #pragma unroll
    for (int g = 0; g < 4; g++) {
        qv[g] = Q[(size_t)b * HID + (kvh * 4 + g) * DD + j];
        sq[g][j] = qv[g];
    }
    __syncthreads();

    float vals[13];
    vals[0] = kv * kv;                           // k_norm^2 partial
    #pragma unroll
    for (int g = 0; g < 4; g++) {
        vals[1 + g] = qv[g] * kv;                // dot partial
        vals[5 + g] = qv[g] * qv[g];             // q_norm^2 partial
    }

    // Hash projections: column j of (x @ hash_w); hash_w reads coalesced.
    float qc[4] = {0.f, 0.f, 0.f, 0.f};
    float kc = 0.f;
    #pragma unroll 4
    for (int d = 0; d < 128; d++) {
        float w  = __ldg(&hw[d * RBIT + j]);
        kc += sk[d] * w;
        #pragma unroll
        for (int g = 0; g < 4; g++) qc[g] += sq[g][d] * w;
    }
    const float kcb = 0.5f * (tanhf(kc) + 1.0f);
    #pragma unroll
    for (int g = 0; g < 4; g++) {
        float qcb = 0.5f * (tanhf(qc[g]) + 1.0f);
        vals[9 + g] = fabsf(qcb - kcb);          // ham partial
    }

    // Block-reduce 13 scalars
    const int lane = j & 31, warp = j >> 5;
    #pragma unroll
    for (int s = 0; s < 13; s++) {
        float v = vals[s];
        #pragma unroll
        for (int o = 16; o > 0; o >>= 1) v += __shfl_down_sync(0xffffffffu, v, o);
        if (lane == 0) racc[s][warp] = v;
    }
    __syncthreads();
    if (j < 13)
        racc[j][0] = racc[j][0] + racc[j][1] + racc[j][2] + racc[j][3];
    __syncthreads();

    if (j < 4) {
        const float inv = 0.08838834764831845f;  // 1/sqrt(128)
        const int g = j;
        const int h = kvh * 4 + g;
        const size_t oidx = (size_t)b * HH + h;
        const float dot = racc[1 + g][0];
        const float qn  = sqrtf(racc[5 + g][0]);
        const float kn  = sqrtf(racc[0][0]);
        const float ham = racc[9 + g][0];
        out[oidx] = dot * inv;
        out[(size_t)BB * HH + oidx] =
            (1.0f - 2.0f * ham / (float)RBIT) * qn * kn * inv;
    }
}

// ---------------------------------------------------------------------------
extern "C" void kernel_launch(void* const* d_in, const int* in_sizes, int n_in,
                              void* d_out, int out_size)
{
    const float* q_hidden = (const float*)d_in[0];
    const float* k_hidden = (const float*)d_in[1];
    const float* q_w      = (const float*)d_in[2];
    const float* q_b      = (const float*)d_in[3];
    const float* k_w      = (const float*)d_in[4];
    const float* k_b      = (const float*)d_in[5];
    const float* hash_w   = (const float*)d_in[6];
    float* out = (float*)d_out;

    void* qp = nullptr;
    void* kp = nullptr;
    cudaGetSymbolAddress(&qp, g_Q);
    cudaGetSymbolAddress(&kp, g_K);
    float* Qbuf = (float*)qp;
    float* Kbuf = (float*)kp;

    // Q projection: [B, HID] = q_hidden @ q_w + q_b
    gemm_bias_kernel<<<dim3(HID / BN, BB / BM), 256>>>(
        q_hidden, q_w, q_b, Qbuf, BB, HID, HID);
    // K projection: [B, KOUT] = k_hidden @ k_w + k_b
    gemm_bias_kernel<<<dim3(KOUT / BN, BB / BM), 256>>>(
        k_hidden, k_w, k_b, Kbuf, BB, KOUT, HID);
    // Fused scores + hash tail
    fused_tail_kernel<<<BB * KVH, 128>>>(Qbuf, Kbuf, hash_w, out);
}

// round 4
// speedup vs baseline: 2.4052x; 2.4052x over previous
#include <cuda_runtime.h>
#include <cuda_bf16.h>
#include <math.h>
#include <stdint.h>

// Problem constants
#define BB    16384
#define HH    32
#define KVH   8
#define DD    128
#define RBIT  128
#define HID   4096      // H*D
#define KOUT  1024      // KVH*D
#define KSPLIT 8192     // stored K (hi|lo planes)
#define KTOT  12288     // logical K' = hi*hi + lo*hi + hi*lo

// ---------------------------------------------------------------------------
// Device scratch (no allocations allowed)
// ---------------------------------------------------------------------------
__device__ __nv_bfloat16 g_Aq[(size_t)BB * KSPLIT];    // 256 MB
__device__ __nv_bfloat16 g_Ak[(size_t)BB * KSPLIT];    // 256 MB
__device__ __nv_bfloat16 g_Wq[(size_t)HID * KSPLIT];   // 64 MB  [N,K] layout
__device__ __nv_bfloat16 g_Wk[(size_t)KOUT * KSPLIT];  // 16 MB  [N,K] layout
__device__ float g_Q[(size_t)BB * HID];                // 256 MB
__device__ float g_K[(size_t)BB * KOUT];               // 64 MB

// ---------------------------------------------------------------------------
// Helpers
// ---------------------------------------------------------------------------
__device__ __forceinline__ uint32_t smem_u32(const void* p) {
    uint32_t a;
    asm("{ .reg .u64 t; cvta.to.shared.u64 t, %1; cvt.u32.u64 %0, t; }"
        : "=r"(a) : "l"(p));
    return a;
}
__device__ __forceinline__ uint32_t sw128(uint32_t off) {
    return off ^ ((off >> 3) & 0x70);   // Swizzle<3,4,3>: 16B chunk ^= row%8
}

#define CP16(dst, src) \
    asm volatile("cp.async.cg.shared.global [%0], [%1], 16;" \
                 :: "r"(dst), "l"(src) : "memory")
#define CP_COMMIT() asm volatile("cp.async.commit_group;" ::: "memory")
#define CP_WAIT(n)  asm volatile("cp.async.wait_group %0;" :: "n"(n) : "memory")

#define LDSM4(r, addr) \
    asm volatile("ldmatrix.sync.aligned.m8n8.x4.shared.b16 {%0,%1,%2,%3}, [%4];" \
                 : "=r"((r)[0]), "=r"((r)[1]), "=r"((r)[2]), "=r"((r)[3]) \
                 : "r"(addr))

__device__ __forceinline__ void mma16816(float* d, const uint32_t* a,
                                         const uint32_t* b) {
    asm volatile(
        "mma.sync.aligned.m16n8k16.row.col.f32.bf16.bf16.f32 "
        "{%0,%1,%2,%3}, {%4,%5,%6,%7}, {%8,%9}, {%0,%1,%2,%3};"
        : "+f"(d[0]), "+f"(d[1]), "+f"(d[2]), "+f"(d[3])
        : "r"(a[0]), "r"(a[1]), "r"(a[2]), "r"(a[3]), "r"(b[0]), "r"(b[1]));
}

// ---------------------------------------------------------------------------
// Conversion: fp32 [rows, 4096] -> bf16 [rows, 8192] = [hi | lo]
// ---------------------------------------------------------------------------
__device__ __forceinline__ uint32_t pack_bf2(__nv_bfloat16 a, __nv_bfloat16 b) {
    __nv_bfloat162 t = __halves2bfloat162(a, b);
    return *reinterpret_cast<uint32_t*>(&t);
}

__global__ __launch_bounds__(256) void split_hl_kernel(
    const float4* __restrict__ X, uint2* __restrict__ Y, size_t n4)
{
    size_t i = (size_t)blockIdx.x * 256 + threadIdx.x;
    if (i >= n4) return;
    size_t row = i >> 10;
    size_t c4  = i & 1023;
    float4 v = X[i];
    __nv_bfloat16 h0 = __float2bfloat16(v.x);
    __nv_bfloat16 h1 = __float2bfloat16(v.y);
    __nv_bfloat16 h2 = __float2bfloat16(v.z);
    __nv_bfloat16 h3 = __float2bfloat16(v.w);
    __nv_bfloat16 l0 = __float2bfloat16(v.x - __bfloat162float(h0));
    __nv_bfloat16 l1 = __float2bfloat16(v.y - __bfloat162float(h1));
    __nv_bfloat16 l2 = __float2bfloat16(v.z - __bfloat162float(h2));
    __nv_bfloat16 l3 = __float2bfloat16(v.w - __bfloat162float(h3));
    uint2 hi = make_uint2(pack_bf2(h0, h1), pack_bf2(h2, h3));
    uint2 lo = make_uint2(pack_bf2(l0, l1), pack_bf2(l2, l3));
    size_t b = row * 2048 + c4;
    Y[b] = hi;
    Y[b + 1024] = lo;
}

// ---------------------------------------------------------------------------
// Conversion + transpose: W fp32 [4096, N] -> Wt bf16 [N, 8192] = [hi | lo]
// ---------------------------------------------------------------------------
__global__ __launch_bounds__(256) void split_w_kernel(
    const float* __restrict__ W, __nv_bfloat16* __restrict__ Wt, int N)
{
    __shared__ float t[32][33];
    int n0 = blockIdx.x * 32, k0 = blockIdx.y * 32;
    int tx = threadIdx.x & 31, ty = threadIdx.x >> 5;
    #pragma unroll
    for (int i = 0; i < 4; i++)
        t[ty + i * 8][tx] = W[(size_t)(k0 + ty + i * 8) * N + n0 + tx];
    __syncthreads();
    #pragma unroll
    for (int i = 0; i < 4; i++) {
        int n = n0 + ty + i * 8;
        int k = k0 + tx;
        float x = t[tx][ty + i * 8];
        __nv_bfloat16 h = __float2bfloat16(x);
        Wt[(size_t)n * KSPLIT + k] = h;
        Wt[(size_t)n * KSPLIT + 4096 + k] = __float2bfloat16(x - __bfloat162float(h));
    }
}

// ---------------------------------------------------------------------------
// HMMA GEMM: C[M,N] = A'[M,K'] @ W'[N,K']^T + bias, split-bf16 K'=12288
// BM=BN=128, BK=64, 4-stage cp.async pipeline, 256 threads (8 warps, 2x4)
// ---------------------------------------------------------------------------
#define BM 128
#define BN 128
#define BKK 64
#define STAGES 4
#define ASTG (BM * BKK * 2)                // 16384 bytes per stage
#define GEMM_SMEM (2 * STAGES * ASTG)      // 131072
#define NIT (KTOT / BKK)                   // 192

__global__ __launch_bounds__(256, 1) void gemm_mma_kernel(
    const __nv_bfloat16* __restrict__ A, const __nv_bfloat16* __restrict__ W,
    const float* __restrict__ bias, float* __restrict__ C, int N)
{
    extern __shared__ char smem[];
    const uint32_t sA = smem_u32(smem);
    const uint32_t sB = sA + STAGES * ASTG;

    const int tid  = threadIdx.x;
    const int lane = tid & 31;
    const int wid  = tid >> 5;
    const int bm = blockIdx.y * BM;
    const int bn = blockIdx.x * BN;
    const int wm = (wid & 1) * 64;          // warp M offset (2 warps)
    const int wn = (wid >> 1) * 32;         // warp N offset (4 warps)

    // cp.async mapping: thread handles rows lr + i*32, 16B chunk lc
    const int lr = tid >> 3;                // 0..31
    const int lc = tid & 7;                 // 0..7
    const __nv_bfloat16* Ab = A + (size_t)(bm + lr) * KSPLIT + lc * 8;
    const __nv_bfloat16* Wb = W + (size_t)(bn + lr) * KSPLIT + lc * 8;
    const uint32_t sdst = sw128(lr * 128 + lc * 16);   // per-thread swizzled base

    float acc[4][4][4];
    #pragma unroll
    for (int mt = 0; mt < 4; mt++)
        #pragma unroll
        for (int nt = 0; nt < 4; nt++)
            #pragma unroll
            for (int e = 0; e < 4; e++) acc[mt][nt][e] = 0.f;

    // ldmatrix per-lane address components (constant across iters)
    const int bi = lane >> 3;               // 8x8 block id 0..3
    const int rr = lane & 7;                // row within block
    const uint32_t a_row = wm + (bi & 1) * 8 + rr;        // + mt*16
    const uint32_t a_col = (bi >> 1) * 16;                // + kp*32
    const uint32_t b_row = wn + (bi >> 1) * 8 + rr;       // + p*16
    const uint32_t b_col = (bi & 1) * 16;                 // + kp*32

    auto load_tile = [&](int stg, int tile) {
        const int kk = tile * BKK;
        const int p  = kk >> 12;
        const int r  = kk & 4095;
        const int ak = r + ((p == 1) ? 4096 : 0);
        const int wk = r + ((p == 2) ? 4096 : 0);
        const uint32_t da = sA + stg * ASTG + sdst;
        const uint32_t db = sB + stg * ASTG + sdst;
        #pragma unroll
        for (int i = 0; i < 4; i++) {
            CP16(da + i * 32 * 128, Ab + (size_t)i * 32 * KSPLIT + ak);
            CP16(db + i * 32 * 128, Wb + (size_t)i * 32 * KSPLIT + wk);
        }
    };

    // Prologue: fill STAGES-1 stages
    #pragma unroll
    for (int s = 0; s < STAGES - 1; s++) {
        load_tile(s, s);
        CP_COMMIT();
    }

    #pragma unroll 1
    for (int i = 0; i < NIT; i++) {
        CP_WAIT(STAGES - 2);
        __syncthreads();            // tile i visible; stage (i-1)%4 fully consumed

        const int nxt = i + STAGES - 1;
        if (nxt < NIT) load_tile(nxt & 3, nxt);
        CP_COMMIT();

        const int stg = i & 3;
        const uint32_t abase = sA + stg * ASTG;
        const uint32_t bbase = sB + stg * ASTG;

        #pragma unroll
        for (int kp = 0; kp < 4; kp++) {
            uint32_t afr[4][4];
            #pragma unroll
            for (int mt = 0; mt < 4; mt++) {
                uint32_t ad = abase +
                    sw128((a_row + mt * 16) * 128 + kp * 32 + a_col);
                LDSM4(afr[mt], ad);
            }
            uint32_t bfr[4][2];
            #pragma unroll
            for (int p = 0; p < 2; p++) {
                uint32_t r4[4];
                uint32_t bd = bbase +
                    sw128((b_row + p * 16) * 128 + kp * 32 + b_col);
                LDSM4(r4, bd);
                bfr[p * 2][0]     = r4[0];
                bfr[p * 2][1]     = r4[1];
                bfr[p * 2 + 1][0] = r4[2];
                bfr[p * 2 + 1][1] = r4[3];
            }
            #pragma unroll
            for (int mt = 0; mt < 4; mt++)
                #pragma unroll
                for (int nt = 0; nt < 4; nt++)
                    mma16816(acc[mt][nt], afr[mt], bfr[nt]);
        }
    }

    // Epilogue: D frag: d0/d1 at (row=gr, col=gc2,+1); d2/d3 at row gr+8
    const int gr  = lane >> 2;
    const int gc2 = (lane & 3) * 2;
    #pragma unroll
    for (int mt = 0; mt < 4; mt++) {
        const int r0 = bm + wm + mt * 16 + gr;
        #pragma unroll
        for (int nt = 0; nt < 4; nt++) {
            const int col = bn + wn + nt * 8 + gc2;
            const float2 bv = *reinterpret_cast<const float2*>(&bias[col]);
            float2 o0 = make_float2(acc[mt][nt][0] + bv.x, acc[mt][nt][1] + bv.y);
            float2 o1 = make_float2(acc[mt][nt][2] + bv.x, acc[mt][nt][3] + bv.y);
            *reinterpret_cast<float2*>(&C[(size_t)r0 * N + col]) = o0;
            *reinterpret_cast<float2*>(&C[(size_t)(r0 + 8) * N + col]) = o1;
        }
    }
}

// ---------------------------------------------------------------------------
// Fused tail (unchanged from passing round)
// ---------------------------------------------------------------------------
__global__ __launch_bounds__(128) void fused_tail_kernel(
    const float* __restrict__ Q, const float* __restrict__ Kp,
    const float* __restrict__ hw, float* __restrict__ out)
{
    const int blk = blockIdx.x;
    const int b   = blk >> 3;
    const int kvh = blk & 7;
    const int j   = threadIdx.x;

    __shared__ float sq[4][128];
    __shared__ float sk[128];
    __shared__ float racc[13][4];

    const float kv = Kp[(size_t)b * KOUT + kvh * DD + j];
    sk[j] = kv;
    float qv[4];
    #pragma unroll
    for (int g = 0; g < 4; g++) {
        qv[g] = Q[(size_t)b * HID + (kvh * 4 + g) * DD + j];
        sq[g][j] = qv[g];
    }
    __syncthreads();

    float vals[13];
    vals[0] = kv * kv;
    #pragma unroll
    for (int g = 0; g < 4; g++) {
        vals[1 + g] = qv[g] * kv;
        vals[5 + g] = qv[g] * qv[g];
    }

    float qc[4] = {0.f, 0.f, 0.f, 0.f};
    float kc = 0.f;
    #pragma unroll 4
    for (int d = 0; d < 128; d++) {
        float w = __ldg(&hw[d * RBIT + j]);
        kc += sk[d] * w;
        #pragma unroll
        for (int g = 0; g < 4; g++) qc[g] += sq[g][d] * w;
    }
    const float kcb = 0.5f * (tanhf(kc) + 1.0f);
    #pragma unroll
    for (int g = 0; g < 4; g++) {
        float qcb = 0.5f * (tanhf(qc[g]) + 1.0f);
        vals[9 + g] = fabsf(qcb - kcb);
    }

    const int lane = j & 31, warp = j >> 5;
    #pragma unroll
    for (int s = 0; s < 13; s++) {
        float v = vals[s];
        #pragma unroll
        for (int o = 16; o > 0; o >>= 1) v += __shfl_down_sync(0xffffffffu, v, o);
        if (lane == 0) racc[s][warp] = v;
    }
    __syncthreads();
    if (j < 13)
        racc[j][0] = racc[j][0] + racc[j][1] + racc[j][2] + racc[j][3];
    __syncthreads();

    if (j < 4) {
        const float inv = 0.08838834764831845f;
        const int g = j;
        const int h = kvh * 4 + g;
        const size_t oidx = (size_t)b * HH + h;
        const float dot = racc[1 + g][0];
        const float qn  = sqrtf(racc[5 + g][0]);
        const float kn  = sqrtf(racc[0][0]);
        const float ham = racc[9 + g][0];
        out[oidx] = dot * inv;
        out[(size_t)BB * HH + oidx] =
            (1.0f - 2.0f * ham / (float)RBIT) * qn * kn * inv;
    }
}

// ---------------------------------------------------------------------------
extern "C" void kernel_launch(void* const* d_in, const int* in_sizes, int n_in,
                              void* d_out, int out_size)
{
    const float* q_hidden = (const float*)d_in[0];
    const float* k_hidden = (const float*)d_in[1];
    const float* q_w      = (const float*)d_in[2];
    const float* q_b      = (const float*)d_in[3];
    const float* k_w      = (const float*)d_in[4];
    const float* k_b      = (const float*)d_in[5];
    const float* hash_w   = (const float*)d_in[6];
    float* out = (float*)d_out;

    void *aq, *ak, *wq, *wk, *qp, *kp;
    cudaGetSymbolAddress(&aq, g_Aq);
    cudaGetSymbolAddress(&ak, g_Ak);
    cudaGetSymbolAddress(&wq, g_Wq);
    cudaGetSymbolAddress(&wk, g_Wk);
    cudaGetSymbolAddress(&qp, g_Q);
    cudaGetSymbolAddress(&kp, g_K);

    cudaFuncSetAttribute(gemm_mma_kernel,
                         cudaFuncAttributeMaxDynamicSharedMemorySize, GEMM_SMEM);

    // 1) split fp32 -> bf16 hi/lo
    const size_t n4 = (size_t)BB * HID / 4;
    split_hl_kernel<<<(unsigned)(n4 / 256), 256>>>((const float4*)q_hidden, (uint2*)aq, n4);
    split_hl_kernel<<<(unsigned)(n4 / 256), 256>>>((const float4*)k_hidden, (uint2*)ak, n4);
    split_w_kernel<<<dim3(HID / 32, HID / 32), 256>>>(q_w, (__nv_bfloat16*)wq, HID);
    split_w_kernel<<<dim3(KOUT / 32, HID / 32), 256>>>(k_w, (__nv_bfloat16*)wk, KOUT);

    // 2) HMMA GEMMs
    gemm_mma_kernel<<<dim3(HID / BN, BB / BM), 256, GEMM_SMEM>>>(
        (const __nv_bfloat16*)aq, (const __nv_bfloat16*)wq, q_b, (float*)qp, HID);
    gemm_mma_kernel<<<dim3(KOUT / BN, BB / BM), 256, GEMM_SMEM>>>(
        (const __nv_bfloat16*)ak, (const __nv_bfloat16*)wk, k_b, (float*)kp, KOUT);

    // 3) fused scores + hash tail
    fused_tail_kernel<<<BB * KVH, 128>>>((const float*)qp, (const float*)kp, hash_w, out);
}

// round 5
// speedup vs baseline: 3.0599x; 1.2722x over previous
#include <cuda_runtime.h>
#include <cuda_bf16.h>
#include <math.h>
#include <stdint.h>

// Problem constants
#define BB    16384
#define HH    32
#define KVH   8
#define DD    128
#define RBIT  128
#define HID   4096      // H*D
#define KOUT  1024      // KVH*D
#define KSPLIT 8192     // stored K (hi|lo planes)
#define KTOT  12288     // logical K' = hi*hi + lo*hi + hi*lo

// ---------------------------------------------------------------------------
// Device scratch (no allocations allowed)
// ---------------------------------------------------------------------------
__device__ __nv_bfloat16 g_Aq[(size_t)BB * KSPLIT];    // 256 MB
__device__ __nv_bfloat16 g_Ak[(size_t)BB * KSPLIT];    // 256 MB
__device__ __nv_bfloat16 g_Wq[(size_t)HID * KSPLIT];   // 64 MB  [N,K] layout
__device__ __nv_bfloat16 g_Wk[(size_t)KOUT * KSPLIT];  // 16 MB  [N,K] layout
__device__ float g_Q[(size_t)BB * HID];                // 256 MB
__device__ float g_K[(size_t)BB * KOUT];               // 64 MB

// ---------------------------------------------------------------------------
// Helpers
// ---------------------------------------------------------------------------
__device__ __forceinline__ uint32_t smem_u32(const void* p) {
    uint32_t a;
    asm("{ .reg .u64 t; cvta.to.shared.u64 t, %1; cvt.u32.u64 %0, t; }"
        : "=r"(a) : "l"(p));
    return a;
}
__device__ __forceinline__ uint32_t sw128(uint32_t off) {
    return off ^ ((off >> 3) & 0x70);   // Swizzle<3,4,3>
}
__device__ __forceinline__ float tanh_fast(float x) {
    float r;
    asm("tanh.approx.f32 %0, %1;" : "=f"(r) : "f"(x));
    return r;
}

#define CP16(dst, src) \
    asm volatile("cp.async.cg.shared.global [%0], [%1], 16;" \
                 :: "r"(dst), "l"(src) : "memory")
#define CP_COMMIT() asm volatile("cp.async.commit_group;" ::: "memory")
#define CP_WAIT(n)  asm volatile("cp.async.wait_group %0;" :: "n"(n) : "memory")

#define LDSM4(r, addr) \
    asm volatile("ldmatrix.sync.aligned.m8n8.x4.shared.b16 {%0,%1,%2,%3}, [%4];" \
                 : "=r"((r)[0]), "=r"((r)[1]), "=r"((r)[2]), "=r"((r)[3]) \
                 : "r"(addr))

__device__ __forceinline__ void mma16816(float* d, const uint32_t* a,
                                         const uint32_t* b) {
    asm volatile(
        "mma.sync.aligned.m16n8k16.row.col.f32.bf16.bf16.f32 "
        "{%0,%1,%2,%3}, {%4,%5,%6,%7}, {%8,%9}, {%0,%1,%2,%3};"
        : "+f"(d[0]), "+f"(d[1]), "+f"(d[2]), "+f"(d[3])
        : "r"(a[0]), "r"(a[1]), "r"(a[2]), "r"(a[3]), "r"(b[0]), "r"(b[1]));
}

// ---------------------------------------------------------------------------
// Conversion: fp32 [rows, 4096] -> bf16 [rows, 8192] = [hi | lo]
// ---------------------------------------------------------------------------
__device__ __forceinline__ uint32_t pack_bf2(__nv_bfloat16 a, __nv_bfloat16 b) {
    __nv_bfloat162 t = __halves2bfloat162(a, b);
    return *reinterpret_cast<uint32_t*>(&t);
}

__global__ __launch_bounds__(256) void split_hl_kernel(
    const float4* __restrict__ X, uint2* __restrict__ Y, size_t n4)
{
    size_t i = (size_t)blockIdx.x * 256 + threadIdx.x;
    if (i >= n4) return;
    size_t row = i >> 10;
    size_t c4  = i & 1023;
    float4 v = X[i];
    __nv_bfloat16 h0 = __float2bfloat16(v.x);
    __nv_bfloat16 h1 = __float2bfloat16(v.y);
    __nv_bfloat16 h2 = __float2bfloat16(v.z);
    __nv_bfloat16 h3 = __float2bfloat16(v.w);
    __nv_bfloat16 l0 = __float2bfloat16(v.x - __bfloat162float(h0));
    __nv_bfloat16 l1 = __float2bfloat16(v.y - __bfloat162float(h1));
    __nv_bfloat16 l2 = __float2bfloat16(v.z - __bfloat162float(h2));
    __nv_bfloat16 l3 = __float2bfloat16(v.w - __bfloat162float(h3));
    uint2 hi = make_uint2(pack_bf2(h0, h1), pack_bf2(h2, h3));
    uint2 lo = make_uint2(pack_bf2(l0, l1), pack_bf2(l2, l3));
    size_t b = row * 2048 + c4;
    Y[b] = hi;
    Y[b + 1024] = lo;
}

// ---------------------------------------------------------------------------
// Conversion + transpose: W fp32 [4096, N] -> Wt bf16 [N, 8192] = [hi | lo]
// ---------------------------------------------------------------------------
__global__ __launch_bounds__(256) void split_w_kernel(
    const float* __restrict__ W, __nv_bfloat16* __restrict__ Wt, int N)
{
    __shared__ float t[32][33];
    int n0 = blockIdx.x * 32, k0 = blockIdx.y * 32;
    int tx = threadIdx.x & 31, ty = threadIdx.x >> 5;
    #pragma unroll
    for (int i = 0; i < 4; i++)
        t[ty + i * 8][tx] = W[(size_t)(k0 + ty + i * 8) * N + n0 + tx];
    __syncthreads();
    #pragma unroll
    for (int i = 0; i < 4; i++) {
        int n = n0 + ty + i * 8;
        int k = k0 + tx;
        float x = t[tx][ty + i * 8];
        __nv_bfloat16 h = __float2bfloat16(x);
        Wt[(size_t)n * KSPLIT + k] = h;
        Wt[(size_t)n * KSPLIT + 4096 + k] = __float2bfloat16(x - __bfloat162float(h));
    }
}

// ---------------------------------------------------------------------------
// HMMA GEMM: C[M,N] = A'[M,K'] @ W'[N,K']^T + bias, split-bf16 K'=12288
// BM=BN=128, BK=64, 3-stage cp.async pipeline, 256 threads, 2 CTAs/SM
// ---------------------------------------------------------------------------
#define BM 128
#define BN 128
#define BKK 64
#define STAGES 3
#define ASTG (BM * BKK * 2)                // 16384 bytes per stage
#define GEMM_SMEM (2 * STAGES * ASTG)      // 98304 (x2 CTAs = 192K <= 228K)
#define NIT (KTOT / BKK)                   // 192

__global__ __launch_bounds__(256, 2) void gemm_mma_kernel(
    const __nv_bfloat16* __restrict__ A, const __nv_bfloat16* __restrict__ W,
    const float* __restrict__ bias, float* __restrict__ C, int N)
{
    extern __shared__ char smem[];
    const uint32_t sA = smem_u32(smem);
    const uint32_t sB = sA + STAGES * ASTG;

    const int tid  = threadIdx.x;
    const int lane = tid & 31;
    const int wid  = tid >> 5;
    const int bm = blockIdx.y * BM;
    const int bn = blockIdx.x * BN;
    const int wm = (wid & 1) * 64;          // warp M offset (2 warps)
    const int wn = (wid >> 1) * 32;         // warp N offset (4 warps)

    const int lr = tid >> 3;                // 0..31
    const int lc = tid & 7;                 // 0..7
    const __nv_bfloat16* Ab = A + (size_t)(bm + lr) * KSPLIT + lc * 8;
    const __nv_bfloat16* Wb = W + (size_t)(bn + lr) * KSPLIT + lc * 8;
    const uint32_t sdst = sw128(lr * 128 + lc * 16);

    float acc[4][4][4];
    #pragma unroll
    for (int mt = 0; mt < 4; mt++)
        #pragma unroll
        for (int nt = 0; nt < 4; nt++)
            #pragma unroll
            for (int e = 0; e < 4; e++) acc[mt][nt][e] = 0.f;

    const int bi = lane >> 3;
    const int rr = lane & 7;
    const uint32_t a_row = wm + (bi & 1) * 8 + rr;
    const uint32_t a_col = (bi >> 1) * 16;
    const uint32_t b_row = wn + (bi >> 1) * 8 + rr;
    const uint32_t b_col = (bi & 1) * 16;

    auto load_tile = [&](int stg, int tile) {
        const int kk = tile * BKK;
        const int p  = kk >> 12;
        const int r  = kk & 4095;
        const int ak = r + ((p == 1) ? 4096 : 0);
        const int wk = r + ((p == 2) ? 4096 : 0);
        const uint32_t da = sA + stg * ASTG + sdst;
        const uint32_t db = sB + stg * ASTG + sdst;
        #pragma unroll
        for (int i = 0; i < 4; i++) {
            CP16(da + i * 32 * 128, Ab + (size_t)i * 32 * KSPLIT + ak);
            CP16(db + i * 32 * 128, Wb + (size_t)i * 32 * KSPLIT + wk);
        }
    };

    #pragma unroll
    for (int s = 0; s < STAGES - 1; s++) {
        load_tile(s, s);
        CP_COMMIT();
    }

    int stg = 0;
    #pragma unroll 1
    for (int i = 0; i < NIT; i++) {
        CP_WAIT(STAGES - 2);
        __syncthreads();

        const int nxt = i + STAGES - 1;
        int nstg = stg + STAGES - 1;
        if (nstg >= STAGES) nstg -= STAGES;
        if (nxt < NIT) load_tile(nstg, nxt);
        CP_COMMIT();

        const uint32_t abase = sA + stg * ASTG;
        const uint32_t bbase = sB + stg * ASTG;

        #pragma unroll
        for (int kp = 0; kp < 4; kp++) {
            uint32_t afr[4][4];
            #pragma unroll
            for (int mt = 0; mt < 4; mt++) {
                uint32_t ad = abase +
                    sw128((a_row + mt * 16) * 128 + kp * 32 + a_col);
                LDSM4(afr[mt], ad);
            }
            uint32_t bfr[4][2];
            #pragma unroll
            for (int p = 0; p < 2; p++) {
                uint32_t r4[4];
                uint32_t bd = bbase +
                    sw128((b_row + p * 16) * 128 + kp * 32 + b_col);
                LDSM4(r4, bd);
                bfr[p * 2][0]     = r4[0];
                bfr[p * 2][1]     = r4[1];
                bfr[p * 2 + 1][0] = r4[2];
                bfr[p * 2 + 1][1] = r4[3];
            }
            #pragma unroll
            for (int mt = 0; mt < 4; mt++)
                #pragma unroll
                for (int nt = 0; nt < 4; nt++)
                    mma16816(acc[mt][nt], afr[mt], bfr[nt]);
        }
        if (++stg == STAGES) stg = 0;
    }

    const int gr  = lane >> 2;
    const int gc2 = (lane & 3) * 2;
    #pragma unroll
    for (int mt = 0; mt < 4; mt++) {
        const int r0 = bm + wm + mt * 16 + gr;
        #pragma unroll
        for (int nt = 0; nt < 4; nt++) {
            const int col = bn + wn + nt * 8 + gc2;
            const float2 bv = *reinterpret_cast<const float2*>(&bias[col]);
            float2 o0 = make_float2(acc[mt][nt][0] + bv.x, acc[mt][nt][1] + bv.y);
            float2 o1 = make_float2(acc[mt][nt][2] + bv.x, acc[mt][nt][3] + bv.y);
            *reinterpret_cast<float2*>(&C[(size_t)r0 * N + col]) = o0;
            *reinterpret_cast<float2*>(&C[(size_t)(r0 + 8) * N + col]) = o1;
        }
    }
}

// ---------------------------------------------------------------------------
// Fused tail v2: one block (128 threads) per (b, kvh).
// Hash phase: warp w owns d in [32w, 32w+32); lane owns 4 rbit columns.
// float4 LDG on hash_w, float4 broadcast LDS on q/k, tanh.approx.
// ---------------------------------------------------------------------------
__global__ __launch_bounds__(128) void fused_tail_kernel(
    const float* __restrict__ Q, const float* __restrict__ Kp,
    const float* __restrict__ hw, float* __restrict__ out)
{
    const int blk = blockIdx.x;
    const int b   = blk >> 3;
    const int kvh = blk & 7;
    const int j   = threadIdx.x;
    const int lane = j & 31, warp = j >> 5;

    __shared__ float sq[4][128];
    __shared__ float sk[128];
    __shared__ float part[4][32][20];   // [warp][lane][src*4 + r]
    __shared__ float racc[13][4];

    const float kv = Kp[(size_t)b * KOUT + kvh * DD + j];
    sk[j] = kv;
    float qv[4];
    #pragma unroll
    for (int g = 0; g < 4; g++) {
        qv[g] = Q[(size_t)b * HID + (kvh * 4 + g) * DD + j];
        sq[g][j] = qv[g];
    }
    __syncthreads();

    // ---- dot / norm partials (9 reductions) ----
    float vals[9];
    vals[0] = kv * kv;
    #pragma unroll
    for (int g = 0; g < 4; g++) {
        vals[1 + g] = qv[g] * kv;
        vals[5 + g] = qv[g] * qv[g];
    }
    #pragma unroll
    for (int s = 0; s < 9; s++) {
        float v = vals[s];
        #pragma unroll
        for (int o = 16; o > 0; o >>= 1) v += __shfl_down_sync(0xffffffffu, v, o);
        if (lane == 0) racc[s][warp] = v;
    }

    // ---- hash projection partials ----
    float av[20];
    #pragma unroll
    for (int s = 0; s < 20; s++) av[s] = 0.f;

    const float* hwp = hw + (size_t)(warp * 32) * RBIT + lane * 4;
    #pragma unroll 2
    for (int i0 = 0; i0 < 32; i0 += 4) {
        const int d0 = warp * 32 + i0;
        float4 k4 = *reinterpret_cast<const float4*>(&sk[d0]);
        float4 q40 = *reinterpret_cast<const float4*>(&sq[0][d0]);
        float4 q41 = *reinterpret_cast<const float4*>(&sq[1][d0]);
        float4 q42 = *reinterpret_cast<const float4*>(&sq[2][d0]);
        float4 q43 = *reinterpret_cast<const float4*>(&sq[3][d0]);
        const float ks[4] = {k4.x, k4.y, k4.z, k4.w};
        const float g0[4] = {q40.x, q40.y, q40.z, q40.w};
        const float g1[4] = {q41.x, q41.y, q41.z, q41.w};
        const float g2[4] = {q42.x, q42.y, q42.z, q42.w};
        const float g3[4] = {q43.x, q43.y, q43.z, q43.w};
        #pragma unroll
        for (int u = 0; u < 4; u++) {
            float4 h4 = __ldg(reinterpret_cast<const float4*>(
                hwp + (size_t)(i0 + u) * RBIT));
            const float hr[4] = {h4.x, h4.y, h4.z, h4.w};
            #pragma unroll
            for (int r = 0; r < 4; r++) {
                av[0 * 4 + r] += g0[u] * hr[r];
                av[1 * 4 + r] += g1[u] * hr[r];
                av[2 * 4 + r] += g2[u] * hr[r];
                av[3 * 4 + r] += g3[u] * hr[r];
                av[4 * 4 + r] += ks[u] * hr[r];
            }
        }
    }
    #pragma unroll
    for (int s = 0; s < 20; s++) part[warp][lane][s] = av[s];
    __syncthreads();

    // ---- per-rbit finalize: thread j owns rbit j = (lane=j>>2, r=j&3) ----
    const int pl = j >> 2, pr = j & 3;
    float ham[4];
    float kc = part[0][pl][16 + pr] + part[1][pl][16 + pr] +
               part[2][pl][16 + pr] + part[3][pl][16 + pr];
    const float kcb = 0.5f * (tanh_fast(kc) + 1.0f);
    #pragma unroll
    for (int g = 0; g < 4; g++) {
        float qc = part[0][pl][g * 4 + pr] + part[1][pl][g * 4 + pr] +
                   part[2][pl][g * 4 + pr] + part[3][pl][g * 4 + pr];
        float qcb = 0.5f * (tanh_fast(qc) + 1.0f);
        ham[g] = fabsf(qcb - kcb);
    }
    #pragma unroll
    for (int g = 0; g < 4; g++) {
        float v = ham[g];
        #pragma unroll
        for (int o = 16; o > 0; o >>= 1) v += __shfl_down_sync(0xffffffffu, v, o);
        if (lane == 0) racc[9 + g][warp] = v;
    }
    __syncthreads();
    if (j < 13)
        racc[j][0] = racc[j][0] + racc[j][1] + racc[j][2] + racc[j][3];
    __syncthreads();

    if (j < 4) {
        const float inv = 0.08838834764831845f;  // 1/sqrt(128)
        const int g = j;
        const int h = kvh * 4 + g;
        const size_t oidx = (size_t)b * HH + h;
        const float dot = racc[1 + g][0];
        const float qn  = sqrtf(racc[5 + g][0]);
        const float kn  = sqrtf(racc[0][0]);
        const float hm  = racc[9 + g][0];
        out[oidx] = dot * inv;
        out[(size_t)BB * HH + oidx] =
            (1.0f - 2.0f * hm / (float)RBIT) * qn * kn * inv;
    }
}

// ---------------------------------------------------------------------------
extern "C" void kernel_launch(void* const* d_in, const int* in_sizes, int n_in,
                              void* d_out, int out_size)
{
    const float* q_hidden = (const float*)d_in[0];
    const float* k_hidden = (const float*)d_in[1];
    const float* q_w      = (const float*)d_in[2];
    const float* q_b      = (const float*)d_in[3];
    const float* k_w      = (const float*)d_in[4];
    const float* k_b      = (const float*)d_in[5];
    const float* hash_w   = (const float*)d_in[6];
    float* out = (float*)d_out;

    void *aq, *ak, *wq, *wk, *qp, *kp;
    cudaGetSymbolAddress(&aq, g_Aq);
    cudaGetSymbolAddress(&ak, g_Ak);
    cudaGetSymbolAddress(&wq, g_Wq);
    cudaGetSymbolAddress(&wk, g_Wk);
    cudaGetSymbolAddress(&qp, g_Q);
    cudaGetSymbolAddress(&kp, g_K);

    cudaFuncSetAttribute(gemm_mma_kernel,
                         cudaFuncAttributeMaxDynamicSharedMemorySize, GEMM_SMEM);

    // 1) split fp32 -> bf16 hi/lo
    const size_t n4 = (size_t)BB * HID / 4;
    split_hl_kernel<<<(unsigned)(n4 / 256), 256>>>((const float4*)q_hidden, (uint2*)aq, n4);
    split_hl_kernel<<<(unsigned)(n4 / 256), 256>>>((const float4*)k_hidden, (uint2*)ak, n4);
    split_w_kernel<<<dim3(HID / 32, HID / 32), 256>>>(q_w, (__nv_bfloat16*)wq, HID);
    split_w_kernel<<<dim3(KOUT / 32, HID / 32), 256>>>(k_w, (__nv_bfloat16*)wk, KOUT);

    // 2) HMMA GEMMs
    gemm_mma_kernel<<<dim3(HID / BN, BB / BM), 256, GEMM_SMEM>>>(
        (const __nv_bfloat16*)aq, (const __nv_bfloat16*)wq, q_b, (float*)qp, HID);
    gemm_mma_kernel<<<dim3(KOUT / BN, BB / BM), 256, GEMM_SMEM>>>(
        (const __nv_bfloat16*)ak, (const __nv_bfloat16*)wk, k_b, (float*)kp, KOUT);

    // 3) fused scores + hash tail
    fused_tail_kernel<<<BB * KVH, 128>>>((const float*)qp, (const float*)kp, hash_w, out);
}

// round 6
// speedup vs baseline: 4.2435x; 1.3868x over previous
#include <cuda_runtime.h>
#include <cuda_fp16.h>
#include <math.h>
#include <stdint.h>

// Problem constants
#define BB    16384
#define HH    32
#define KVH   8
#define DD    128
#define RBIT  128
#define HID   4096      // H*D
#define KOUT  1024      // KVH*D
#define KSPLIT 8192     // A stored K (hi|lo fp16 planes)
#define WK    4096      // W stored K (hi plane only)

// ---------------------------------------------------------------------------
// Device scratch (no allocations allowed)
// ---------------------------------------------------------------------------
__device__ __half g_Aq[(size_t)BB * KSPLIT];    // 256 MB
__device__ __half g_Ak[(size_t)BB * KSPLIT];    // 256 MB
__device__ __half g_Wq[(size_t)HID * WK];       // 32 MB  [N,K] layout
__device__ __half g_Wk[(size_t)KOUT * WK];      // 8 MB   [N,K] layout
__device__ float g_Q[(size_t)BB * HID];         // 256 MB
__device__ float g_K[(size_t)BB * KOUT];        // 64 MB

// ---------------------------------------------------------------------------
// Helpers
// ---------------------------------------------------------------------------
__device__ __forceinline__ uint32_t smem_u32(const void* p) {
    uint32_t a;
    asm("{ .reg .u64 t; cvta.to.shared.u64 t, %1; cvt.u32.u64 %0, t; }"
        : "=r"(a) : "l"(p));
    return a;
}
__device__ __forceinline__ uint32_t sw128(uint32_t off) {
    return off ^ ((off >> 3) & 0x70);   // Swizzle<3,4,3>
}
__device__ __forceinline__ float tanh_fast(float x) {
    float r;
    asm("tanh.approx.f32 %0, %1;" : "=f"(r) : "f"(x));
    return r;
}

#define CP16(dst, src) \
    asm volatile("cp.async.cg.shared.global [%0], [%1], 16;" \
                 :: "r"(dst), "l"(src) : "memory")
#define CP_COMMIT() asm volatile("cp.async.commit_group;" ::: "memory")
#define CP_WAIT(n)  asm volatile("cp.async.wait_group %0;" :: "n"(n) : "memory")

#define LDSM4(r, addr) \
    asm volatile("ldmatrix.sync.aligned.m8n8.x4.shared.b16 {%0,%1,%2,%3}, [%4];" \
                 : "=r"((r)[0]), "=r"((r)[1]), "=r"((r)[2]), "=r"((r)[3]) \
                 : "r"(addr))

__device__ __forceinline__ void mma16816(float* d, const uint32_t* a,
                                         const uint32_t* b) {
    asm volatile(
        "mma.sync.aligned.m16n8k16.row.col.f32.f16.f16.f32 "
        "{%0,%1,%2,%3}, {%4,%5,%6,%7}, {%8,%9}, {%0,%1,%2,%3};"
        : "+f"(d[0]), "+f"(d[1]), "+f"(d[2]), "+f"(d[3])
        : "r"(a[0]), "r"(a[1]), "r"(a[2]), "r"(a[3]), "r"(b[0]), "r"(b[1]));
}

// ---------------------------------------------------------------------------
// Conversion: fp32 [rows, 4096] -> fp16 [rows, 8192] = [hi | lo]
// ---------------------------------------------------------------------------
__device__ __forceinline__ uint32_t pack_h2(__half a, __half b) {
    __half2 t = __halves2half2(a, b);
    return *reinterpret_cast<uint32_t*>(&t);
}

__global__ __launch_bounds__(256) void split_hl_kernel(
    const float4* __restrict__ X, uint2* __restrict__ Y, size_t n4)
{
    size_t i = (size_t)blockIdx.x * 256 + threadIdx.x;
    if (i >= n4) return;
    size_t row = i >> 10;          // 1024 float4 per input row
    size_t c4  = i & 1023;
    float4 v = X[i];
    __half h0 = __float2half(v.x);
    __half h1 = __float2half(v.y);
    __half h2 = __float2half(v.z);
    __half h3 = __float2half(v.w);
    __half l0 = __float2half(v.x - __half2float(h0));
    __half l1 = __float2half(v.y - __half2float(h1));
    __half l2 = __float2half(v.z - __half2float(h2));
    __half l3 = __float2half(v.w - __half2float(h3));
    uint2 hi = make_uint2(pack_h2(h0, h1), pack_h2(h2, h3));
    uint2 lo = make_uint2(pack_h2(l0, l1), pack_h2(l2, l3));
    size_t b = row * 2048 + c4;    // 2048 uint2 per output row (8192 fp16)
    Y[b] = hi;
    Y[b + 1024] = lo;              // lo plane at +4096 elements
}

// ---------------------------------------------------------------------------
// Conversion + transpose: W fp32 [4096, N] -> Wt fp16 [N, 4096] (hi only)
// ---------------------------------------------------------------------------
__global__ __launch_bounds__(256) void split_w_kernel(
    const float* __restrict__ W, __half* __restrict__ Wt, int N)
{
    __shared__ float t[32][33];
    int n0 = blockIdx.x * 32, k0 = blockIdx.y * 32;
    int tx = threadIdx.x & 31, ty = threadIdx.x >> 5;
    #pragma unroll
    for (int i = 0; i < 4; i++)
        t[ty + i * 8][tx] = W[(size_t)(k0 + ty + i * 8) * N + n0 + tx];
    __syncthreads();
    #pragma unroll
    for (int i = 0; i < 4; i++) {
        int n = n0 + ty + i * 8;
        int k = k0 + tx;
        Wt[(size_t)n * WK + k] = __float2half(t[tx][ty + i * 8]);
    }
}

// ---------------------------------------------------------------------------
// HMMA GEMM: C[M,N] = (A_hi + A_lo)[M,K'] @ W_hi[N,K]^T + bias
// A K' = 8192 ([hi|lo]); W K = 4096, indexed k & 4095 (2nd pass L2-hits).
// BM=BN=128, BK=64, 3-stage cp.async pipeline, 256 threads, 2 CTAs/SM
// ---------------------------------------------------------------------------
#define BM 128
#define BN 128
#define BKK 64
#define STAGES 3
#define ASTG (BM * BKK * 2)                // 16384 bytes per stage
#define GEMM_SMEM (2 * STAGES * ASTG)      // 98304 (x2 CTAs = 192K <= 228K)
#define NIT (KSPLIT / BKK)                 // 128

__global__ __launch_bounds__(256, 2) void gemm_mma_kernel(
    const __half* __restrict__ A, const __half* __restrict__ W,
    const float* __restrict__ bias, float* __restrict__ C, int N)
{
    extern __shared__ char smem[];
    const uint32_t sA = smem_u32(smem);
    const uint32_t sB = sA + STAGES * ASTG;

    const int tid  = threadIdx.x;
    const int lane = tid & 31;
    const int wid  = tid >> 5;
    const int bm = blockIdx.y * BM;
    const int bn = blockIdx.x * BN;
    const int wm = (wid & 1) * 64;          // warp M offset (2 warps)
    const int wn = (wid >> 1) * 32;         // warp N offset (4 warps)

    const int lr = tid >> 3;                // 0..31
    const int lc = tid & 7;                 // 0..7
    const __half* Ab = A + (size_t)(bm + lr) * KSPLIT + lc * 8;
    const __half* Wb = W + (size_t)(bn + lr) * WK + lc * 8;
    const uint32_t sdst = sw128(lr * 128 + lc * 16);

    float acc[4][4][4];
    #pragma unroll
    for (int mt = 0; mt < 4; mt++)
        #pragma unroll
        for (int nt = 0; nt < 4; nt++)
            #pragma unroll
            for (int e = 0; e < 4; e++) acc[mt][nt][e] = 0.f;

    const int bi = lane >> 3;
    const int rr = lane & 7;
    const uint32_t a_row = wm + (bi & 1) * 8 + rr;
    const uint32_t a_col = (bi >> 1) * 16;
    const uint32_t b_row = wn + (bi >> 1) * 8 + rr;
    const uint32_t b_col = (bi & 1) * 16;

    auto load_tile = [&](int stg, int tile) {
        const int ak = tile * BKK;          // 0..8191
        const int wk = ak & (WK - 1);       // wrap to hi plane
        const uint32_t da = sA + stg * ASTG + sdst;
        const uint32_t db = sB + stg * ASTG + sdst;
        #pragma unroll
        for (int i = 0; i < 4; i++) {
            CP16(da + i * 32 * 128, Ab + (size_t)i * 32 * KSPLIT + ak);
            CP16(db + i * 32 * 128, Wb + (size_t)i * 32 * WK + wk);
        }
    };

    #pragma unroll
    for (int s = 0; s < STAGES - 1; s++) {
        load_tile(s, s);
        CP_COMMIT();
    }

    int stg = 0;
    #pragma unroll 1
    for (int i = 0; i < NIT; i++) {
        CP_WAIT(STAGES - 2);
        __syncthreads();

        const int nxt = i + STAGES - 1;
        int nstg = stg + STAGES - 1;
        if (nstg >= STAGES) nstg -= STAGES;
        if (nxt < NIT) load_tile(nstg, nxt);
        CP_COMMIT();

        const uint32_t abase = sA + stg * ASTG;
        const uint32_t bbase = sB + stg * ASTG;

        #pragma unroll
        for (int kp = 0; kp < 4; kp++) {
            uint32_t afr[4][4];
            #pragma unroll
            for (int mt = 0; mt < 4; mt++) {
                uint32_t ad = abase +
                    sw128((a_row + mt * 16) * 128 + kp * 32 + a_col);
                LDSM4(afr[mt], ad);
            }
            uint32_t bfr[4][2];
            #pragma unroll
            for (int p = 0; p < 2; p++) {
                uint32_t r4[4];
                uint32_t bd = bbase +
                    sw128((b_row + p * 16) * 128 + kp * 32 + b_col);
                LDSM4(r4, bd);
                bfr[p * 2][0]     = r4[0];
                bfr[p * 2][1]     = r4[1];
                bfr[p * 2 + 1][0] = r4[2];
                bfr[p * 2 + 1][1] = r4[3];
            }
            #pragma unroll
            for (int mt = 0; mt < 4; mt++)
                #pragma unroll
                for (int nt = 0; nt < 4; nt++)
                    mma16816(acc[mt][nt], afr[mt], bfr[nt]);
        }
        if (++stg == STAGES) stg = 0;
    }

    const int gr  = lane >> 2;
    const int gc2 = (lane & 3) * 2;
    #pragma unroll
    for (int mt = 0; mt < 4; mt++) {
        const int r0 = bm + wm + mt * 16 + gr;
        #pragma unroll
        for (int nt = 0; nt < 4; nt++) {
            const int col = bn + wn + nt * 8 + gc2;
            const float2 bv = *reinterpret_cast<const float2*>(&bias[col]);
            float2 o0 = make_float2(acc[mt][nt][0] + bv.x, acc[mt][nt][1] + bv.y);
            float2 o1 = make_float2(acc[mt][nt][2] + bv.x, acc[mt][nt][3] + bv.y);
            *reinterpret_cast<float2*>(&C[(size_t)r0 * N + col]) = o0;
            *reinterpret_cast<float2*>(&C[(size_t)(r0 + 8) * N + col]) = o1;
        }
    }
}

// ---------------------------------------------------------------------------
// Fused tail: one block (128 threads) per (b, kvh).
// Hash phase: warp w owns d in [32w, 32w+32); lane owns 4 rbit columns.
// ---------------------------------------------------------------------------
__global__ __launch_bounds__(128) void fused_tail_kernel(
    const float* __restrict__ Q, const float* __restrict__ Kp,
    const float* __restrict__ hw, float* __restrict__ out)
{
    const int blk = blockIdx.x;
    const int b   = blk >> 3;
    const int kvh = blk & 7;
    const int j   = threadIdx.x;
    const int lane = j & 31, warp = j >> 5;

    __shared__ float sq[4][128];
    __shared__ float sk[128];
    __shared__ float part[4][32][20];   // [warp][lane][src*4 + r]
    __shared__ float racc[13][4];

    const float kv = Kp[(size_t)b * KOUT + kvh * DD + j];
    sk[j] = kv;
    float qv[4];
    #pragma unroll
    for (int g = 0; g < 4; g++) {
        qv[g] = Q[(size_t)b * HID + (kvh * 4 + g) * DD + j];
        sq[g][j] = qv[g];
    }
    __syncthreads();

    // ---- dot / norm partials (9 reductions) ----
    float vals[9];
    vals[0] = kv * kv;
    #pragma unroll
    for (int g = 0; g < 4; g++) {
        vals[1 + g] = qv[g] * kv;
        vals[5 + g] = qv[g] * qv[g];
    }
    #pragma unroll
    for (int s = 0; s < 9; s++) {
        float v = vals[s];
        #pragma unroll
        for (int o = 16; o > 0; o >>= 1) v += __shfl_down_sync(0xffffffffu, v, o);
        if (lane == 0) racc[s][warp] = v;
    }

    // ---- hash projection partials ----
    float av[20];
    #pragma unroll
    for (int s = 0; s < 20; s++) av[s] = 0.f;

    const float* hwp = hw + (size_t)(warp * 32) * RBIT + lane * 4;
    #pragma unroll 2
    for (int i0 = 0; i0 < 32; i0 += 4) {
        const int d0 = warp * 32 + i0;
        float4 k4 = *reinterpret_cast<const float4*>(&sk[d0]);
        float4 q40 = *reinterpret_cast<const float4*>(&sq[0][d0]);
        float4 q41 = *reinterpret_cast<const float4*>(&sq[1][d0]);
        float4 q42 = *reinterpret_cast<const float4*>(&sq[2][d0]);
        float4 q43 = *reinterpret_cast<const float4*>(&sq[3][d0]);
        const float ks[4] = {k4.x, k4.y, k4.z, k4.w};
        const float g0[4] = {q40.x, q40.y, q40.z, q40.w};
        const float g1[4] = {q41.x, q41.y, q41.z, q41.w};
        const float g2[4] = {q42.x, q42.y, q42.z, q42.w};
        const float g3[4] = {q43.x, q43.y, q43.z, q43.w};
        #pragma unroll
        for (int u = 0; u < 4; u++) {
            float4 h4 = __ldg(reinterpret_cast<const float4*>(
                hwp + (size_t)(i0 + u) * RBIT));
            const float hr[4] = {h4.x, h4.y, h4.z, h4.w};
            #pragma unroll
            for (int r = 0; r < 4; r++) {
                av[0 * 4 + r] += g0[u] * hr[r];
                av[1 * 4 + r] += g1[u] * hr[r];
                av[2 * 4 + r] += g2[u] * hr[r];
                av[3 * 4 + r] += g3[u] * hr[r];
                av[4 * 4 + r] += ks[u] * hr[r];
            }
        }
    }
    #pragma unroll
    for (int s = 0; s < 20; s++) part[warp][lane][s] = av[s];
    __syncthreads();

    // ---- per-rbit finalize: thread j owns rbit j = (lane=j>>2, r=j&3) ----
    const int pl = j >> 2, pr = j & 3;
    float ham[4];
    float kc = part[0][pl][16 + pr] + part[1][pl][16 + pr] +
               part[2][pl][16 + pr] + part[3][pl][16 + pr];
    const float kcb = 0.5f * (tanh_fast(kc) + 1.0f);
    #pragma unroll
    for (int g = 0; g < 4; g++) {
        float qc = part[0][pl][g * 4 + pr] + part[1][pl][g * 4 + pr] +
                   part[2][pl][g * 4 + pr] + part[3][pl][g * 4 + pr];
        float qcb = 0.5f * (tanh_fast(qc) + 1.0f);
        ham[g] = fabsf(qcb - kcb);
    }
    #pragma unroll
    for (int g = 0; g < 4; g++) {
        float v = ham[g];
        #pragma unroll
        for (int o = 16; o > 0; o >>= 1) v += __shfl_down_sync(0xffffffffu, v, o);
        if (lane == 0) racc[9 + g][warp] = v;
    }
    __syncthreads();
    if (j < 13)
        racc[j][0] = racc[j][0] + racc[j][1] + racc[j][2] + racc[j][3];
    __syncthreads();

    if (j < 4) {
        const float inv = 0.08838834764831845f;  // 1/sqrt(128)
        const int g = j;
        const int h = kvh * 4 + g;
        const size_t oidx = (size_t)b * HH + h;
        const float dot = racc[1 + g][0];
        const float qn  = sqrtf(racc[5 + g][0]);
        const float kn  = sqrtf(racc[0][0]);
        const float hm  = racc[9 + g][0];
        out[oidx] = dot * inv;
        out[(size_t)BB * HH + oidx] =
            (1.0f - 2.0f * hm / (float)RBIT) * qn * kn * inv;
    }
}

// ---------------------------------------------------------------------------
extern "C" void kernel_launch(void* const* d_in, const int* in_sizes, int n_in,
                              void* d_out, int out_size)
{
    const float* q_hidden = (const float*)d_in[0];
    const float* k_hidden = (const float*)d_in[1];
    const float* q_w      = (const float*)d_in[2];
    const float* q_b      = (const float*)d_in[3];
    const float* k_w      = (const float*)d_in[4];
    const float* k_b      = (const float*)d_in[5];
    const float* hash_w   = (const float*)d_in[6];
    float* out = (float*)d_out;

    void *aq, *ak, *wq, *wk, *qp, *kp;
    cudaGetSymbolAddress(&aq, g_Aq);
    cudaGetSymbolAddress(&ak, g_Ak);
    cudaGetSymbolAddress(&wq, g_Wq);
    cudaGetSymbolAddress(&wk, g_Wk);
    cudaGetSymbolAddress(&qp, g_Q);
    cudaGetSymbolAddress(&kp, g_K);

    cudaFuncSetAttribute(gemm_mma_kernel,
                         cudaFuncAttributeMaxDynamicSharedMemorySize, GEMM_SMEM);

    // 1) split fp32 -> fp16 hi/lo (A), fp16 hi + transpose (W)
    const size_t n4 = (size_t)BB * HID / 4;
    split_hl_kernel<<<(unsigned)(n4 / 256), 256>>>((const float4*)q_hidden, (uint2*)aq, n4);
    split_hl_kernel<<<(unsigned)(n4 / 256), 256>>>((const float4*)k_hidden, (uint2*)ak, n4);
    split_w_kernel<<<dim3(HID / 32, HID / 32), 256>>>(q_w, (__half*)wq, HID);
    split_w_kernel<<<dim3(KOUT / 32, HID / 32), 256>>>(k_w, (__half*)wk, KOUT);

    // 2) HMMA GEMMs (fp16 split, 2 logical passes)
    gemm_mma_kernel<<<dim3(HID / BN, BB / BM), 256, GEMM_SMEM>>>(
        (const __half*)aq, (const __half*)wq, q_b, (float*)qp, HID);
    gemm_mma_kernel<<<dim3(KOUT / BN, BB / BM), 256, GEMM_SMEM>>>(
        (const __half*)ak, (const __half*)wk, k_b, (float*)kp, KOUT);

    // 3) fused scores + hash tail
    fused_tail_kernel<<<BB * KVH, 128>>>((const float*)qp, (const float*)kp, hash_w, out);
}

// round 7
// speedup vs baseline: 4.7521x; 1.1199x over previous
#include <cuda_runtime.h>
#include <cuda_fp16.h>
#include <math.h>
#include <stdint.h>

// Problem constants
#define BB    16384
#define HH    32
#define KVH   8
#define DD    128
#define RBIT  128
#define HID   4096      // H*D
#define KOUT  1024      // KVH*D
#define KSPLIT 8192     // A stored K (hi|lo fp16 planes)
#define WK    4096      // W stored K (hi plane only)

// ---------------------------------------------------------------------------
// Device scratch (no allocations allowed)
// ---------------------------------------------------------------------------
__device__ __half g_Aq[(size_t)BB * KSPLIT];    // 256 MB
__device__ __half g_Ak[(size_t)BB * KSPLIT];    // 256 MB
__device__ __half g_Wq[(size_t)HID * WK];       // 32 MB  [N,K] layout
__device__ __half g_Wk[(size_t)KOUT * WK];      // 8 MB   [N,K] layout
__device__ float g_Q[(size_t)BB * HID];         // 256 MB
__device__ float g_K[(size_t)BB * KOUT];        // 64 MB
__device__ __half g_hwT[RBIT * DD];             // 32 KB  hash_w^T [r][d] fp16

// ---------------------------------------------------------------------------
// Helpers
// ---------------------------------------------------------------------------
__device__ __forceinline__ uint32_t smem_u32(const void* p) {
    uint32_t a;
    asm("{ .reg .u64 t; cvta.to.shared.u64 t, %1; cvt.u32.u64 %0, t; }"
        : "=r"(a) : "l"(p));
    return a;
}
__device__ __forceinline__ uint32_t sw128(uint32_t off) {
    return off ^ ((off >> 3) & 0x70);   // Swizzle<3,4,3>
}
__device__ __forceinline__ float tanh_fast(float x) {
    float r;
    asm("tanh.approx.f32 %0, %1;" : "=f"(r) : "f"(x));
    return r;
}

#define CP16(dst, src) \
    asm volatile("cp.async.cg.shared.global [%0], [%1], 16;" \
                 :: "r"(dst), "l"(src) : "memory")
#define CP_COMMIT() asm volatile("cp.async.commit_group;" ::: "memory")
#define CP_WAIT(n)  asm volatile("cp.async.wait_group %0;" :: "n"(n) : "memory")

#define LDSM4(r, addr) \
    asm volatile("ldmatrix.sync.aligned.m8n8.x4.shared.b16 {%0,%1,%2,%3}, [%4];" \
                 : "=r"((r)[0]), "=r"((r)[1]), "=r"((r)[2]), "=r"((r)[3]) \
                 : "r"(addr))

__device__ __forceinline__ void mma16816(float* d, const uint32_t* a,
                                         const uint32_t* b) {
    asm volatile(
        "mma.sync.aligned.m16n8k16.row.col.f32.f16.f16.f32 "
        "{%0,%1,%2,%3}, {%4,%5,%6,%7}, {%8,%9}, {%0,%1,%2,%3};"
        : "+f"(d[0]), "+f"(d[1]), "+f"(d[2]), "+f"(d[3])
        : "r"(a[0]), "r"(a[1]), "r"(a[2]), "r"(a[3]), "r"(b[0]), "r"(b[1]));
}

__device__ __forceinline__ uint32_t pack_h2(__half a, __half b) {
    __half2 t = __halves2half2(a, b);
    return *reinterpret_cast<uint32_t*>(&t);
}

// ---------------------------------------------------------------------------
// Conversion: fp32 [rows, 4096] -> fp16 [rows, 8192] = [hi | lo]
// ---------------------------------------------------------------------------
__global__ __launch_bounds__(256) void split_hl_kernel(
    const float4* __restrict__ X, uint2* __restrict__ Y, size_t n4)
{
    size_t i = (size_t)blockIdx.x * 256 + threadIdx.x;
    if (i >= n4) return;
    size_t row = i >> 10;
    size_t c4  = i & 1023;
    float4 v = X[i];
    __half h0 = __float2half(v.x);
    __half h1 = __float2half(v.y);
    __half h2 = __float2half(v.z);
    __half h3 = __float2half(v.w);
    __half l0 = __float2half(v.x - __half2float(h0));
    __half l1 = __float2half(v.y - __half2float(h1));
    __half l2 = __float2half(v.z - __half2float(h2));
    __half l3 = __float2half(v.w - __half2float(h3));
    uint2 hi = make_uint2(pack_h2(h0, h1), pack_h2(h2, h3));
    uint2 lo = make_uint2(pack_h2(l0, l1), pack_h2(l2, l3));
    size_t b = row * 2048 + c4;
    Y[b] = hi;
    Y[b + 1024] = lo;
}

// ---------------------------------------------------------------------------
// Conversion + transpose: W fp32 [4096, N] -> Wt fp16 [N, 4096] (hi only)
// ---------------------------------------------------------------------------
__global__ __launch_bounds__(256) void split_w_kernel(
    const float* __restrict__ W, __half* __restrict__ Wt, int N)
{
    __shared__ float t[32][33];
    int n0 = blockIdx.x * 32, k0 = blockIdx.y * 32;
    int tx = threadIdx.x & 31, ty = threadIdx.x >> 5;
    #pragma unroll
    for (int i = 0; i < 4; i++)
        t[ty + i * 8][tx] = W[(size_t)(k0 + ty + i * 8) * N + n0 + tx];
    __syncthreads();
    #pragma unroll
    for (int i = 0; i < 4; i++) {
        int n = n0 + ty + i * 8;
        int k = k0 + tx;
        Wt[(size_t)n * WK + k] = __float2half(t[tx][ty + i * 8]);
    }
}

// ---------------------------------------------------------------------------
// hash_w fp32 [d=128][r=128] -> hwT fp16 [r][d]
// ---------------------------------------------------------------------------
__global__ __launch_bounds__(256) void hw16_kernel(
    const float* __restrict__ hw, __half* __restrict__ hwT)
{
    int t = blockIdx.x * 256 + threadIdx.x;     // 16384 total
    int d = t >> 7, r = t & 127;
    hwT[r * DD + d] = __float2half(hw[d * RBIT + r]);
}

// ---------------------------------------------------------------------------
// HMMA GEMM: C[M,N] = (A_hi + A_lo)[M,K'] @ W_hi[N,K]^T + bias
// A K' = 8192 ([hi|lo]); W K = 4096, indexed k & 4095 (2nd pass L2-hits).
// BM=BN=128, BK=64, 3-stage cp.async pipeline, 256 threads, 2 CTAs/SM
// ---------------------------------------------------------------------------
#define BM 128
#define BN 128
#define BKK 64
#define STAGES 3
#define ASTG (BM * BKK * 2)                // 16384 bytes per stage
#define GEMM_SMEM (2 * STAGES * ASTG)      // 98304
#define NIT (KSPLIT / BKK)                 // 128

__global__ __launch_bounds__(256, 2) void gemm_mma_kernel(
    const __half* __restrict__ A, const __half* __restrict__ W,
    const float* __restrict__ bias, float* __restrict__ C, int N)
{
    extern __shared__ char smem[];
    const uint32_t sA = smem_u32(smem);
    const uint32_t sB = sA + STAGES * ASTG;

    const int tid  = threadIdx.x;
    const int lane = tid & 31;
    const int wid  = tid >> 5;
    const int bm = blockIdx.y * BM;
    const int bn = blockIdx.x * BN;
    const int wm = (wid & 1) * 64;
    const int wn = (wid >> 1) * 32;

    const int lr = tid >> 3;
    const int lc = tid & 7;
    const __half* Ab = A + (size_t)(bm + lr) * KSPLIT + lc * 8;
    const __half* Wb = W + (size_t)(bn + lr) * WK + lc * 8;
    const uint32_t sdst = sw128(lr * 128 + lc * 16);

    float acc[4][4][4];
    #pragma unroll
    for (int mt = 0; mt < 4; mt++)
        #pragma unroll
        for (int nt = 0; nt < 4; nt++)
            #pragma unroll
            for (int e = 0; e < 4; e++) acc[mt][nt][e] = 0.f;

    const int bi = lane >> 3;
    const int rr = lane & 7;
    const uint32_t a_row = wm + (bi & 1) * 8 + rr;
    const uint32_t a_col = (bi >> 1) * 16;
    const uint32_t b_row = wn + (bi >> 1) * 8 + rr;
    const uint32_t b_col = (bi & 1) * 16;

    auto load_tile = [&](int stg, int tile) {
        const int ak = tile * BKK;
        const int wk = ak & (WK - 1);
        const uint32_t da = sA + stg * ASTG + sdst;
        const uint32_t db = sB + stg * ASTG + sdst;
        #pragma unroll
        for (int i = 0; i < 4; i++) {
            CP16(da + i * 32 * 128, Ab + (size_t)i * 32 * KSPLIT + ak);
            CP16(db + i * 32 * 128, Wb + (size_t)i * 32 * WK + wk);
        }
    };

    #pragma unroll
    for (int s = 0; s < STAGES - 1; s++) {
        load_tile(s, s);
        CP_COMMIT();
    }

    int stg = 0;
    #pragma unroll 1
    for (int i = 0; i < NIT; i++) {
        CP_WAIT(STAGES - 2);
        __syncthreads();

        const int nxt = i + STAGES - 1;
        int nstg = stg + STAGES - 1;
        if (nstg >= STAGES) nstg -= STAGES;
        if (nxt < NIT) load_tile(nstg, nxt);
        CP_COMMIT();

        const uint32_t abase = sA + stg * ASTG;
        const uint32_t bbase = sB + stg * ASTG;

        #pragma unroll
        for (int kp = 0; kp < 4; kp++) {
            uint32_t afr[4][4];
            #pragma unroll
            for (int mt = 0; mt < 4; mt++) {
                uint32_t ad = abase +
                    sw128((a_row + mt * 16) * 128 + kp * 32 + a_col);
                LDSM4(afr[mt], ad);
            }
            uint32_t bfr[4][2];
            #pragma unroll
            for (int p = 0; p < 2; p++) {
                uint32_t r4[4];
                uint32_t bd = bbase +
                    sw128((b_row + p * 16) * 128 + kp * 32 + b_col);
                LDSM4(r4, bd);
                bfr[p * 2][0]     = r4[0];
                bfr[p * 2][1]     = r4[1];
                bfr[p * 2 + 1][0] = r4[2];
                bfr[p * 2 + 1][1] = r4[3];
            }
            #pragma unroll
            for (int mt = 0; mt < 4; mt++)
                #pragma unroll
                for (int nt = 0; nt < 4; nt++)
                    mma16816(acc[mt][nt], afr[mt], bfr[nt]);
        }
        if (++stg == STAGES) stg = 0;
    }

    const int gr  = lane >> 2;
    const int gc2 = (lane & 3) * 2;
    #pragma unroll
    for (int mt = 0; mt < 4; mt++) {
        const int r0 = bm + wm + mt * 16 + gr;
        #pragma unroll
        for (int nt = 0; nt < 4; nt++) {
            const int col = bn + wn + nt * 8 + gc2;
            const float2 bv = *reinterpret_cast<const float2*>(&bias[col]);
            float2 o0 = make_float2(acc[mt][nt][0] + bv.x, acc[mt][nt][1] + bv.y);
            float2 o1 = make_float2(acc[mt][nt][2] + bv.x, acc[mt][nt][3] + bv.y);
            *reinterpret_cast<float2*>(&C[(size_t)r0 * N + col]) = o0;
            *reinterpret_cast<float2*>(&C[(size_t)(r0 + 8) * N + col]) = o1;
        }
    }
}

// ---------------------------------------------------------------------------
// HMMA tail: one block per (16 b-rows, kvh). 5 warps (160 threads).
// A tile [80][128] fp16: warps 0-3 = q heads g=0..3 (16 rows each),
// warp 4 = k rows. codes = tanh(A @ hwT^T)*0.5+0.5 via HMMA; dots/norms fp32.
// ---------------------------------------------------------------------------
#define T_A_OFF    0                        // 2 planes of [80][64] fp16
#define T_A_PLANE  10240
#define T_HW_OFF   20480                    // 2 planes of [128][64] fp16
#define T_HW_PLANE 16384
#define T_CODE_OFF 53248                    // [80][132] fp32
#define T_CODE_STR 132
#define T_SN_OFF   (T_CODE_OFF + 80 * T_CODE_STR * 4)   // 95488, [80] fp32
#define TAIL_SMEM  (T_SN_OFF + 320 + 64)

__global__ __launch_bounds__(160, 2) void tail_mma_kernel(
    const float* __restrict__ Q, const float* __restrict__ Kp,
    const __half* __restrict__ hwT, float* __restrict__ out)
{
    extern __shared__ char ts[];
    const uint32_t sbase = smem_u32(ts);
    float* codes = reinterpret_cast<float*>(ts + T_CODE_OFF);
    float* snorm = reinterpret_cast<float*>(ts + T_SN_OFF);

    const int tid  = threadIdx.x;
    const int lane = tid & 31;
    const int wid  = tid >> 5;
    const int b0   = (blockIdx.x >> 3) * 16;
    const int kvh  = blockIdx.x & 7;
    const float inv = 0.08838834764831845f;    // 1/sqrt(128)

    // ---- load hwT into 2 swizzled planes [128 r][64 d] each ----
    for (int c = tid; c < 2048; c += 160) {     // 16B chunks
        int row = c >> 4, seg = c & 15;
        int pl = seg >> 3;
        uint4 v = *reinterpret_cast<const uint4*>(
            hwT + (size_t)row * DD + pl * 64 + (seg & 7) * 8);
        uint32_t off = T_HW_OFF + pl * T_HW_PLANE +
                       sw128(row * 128 + (seg & 7) * 16);
        *reinterpret_cast<uint4*>(ts + off) = v;
    }

    // ---- load activations, compute dot/norms fp32, stage fp16 tiles ----
    {
        const int i = lane >> 1;             // row 0..15
        const int h = lane & 1;              // 64-col half
        const int b = b0 + i;
        const float* kptr = Kp + (size_t)b * KOUT + kvh * DD + h * 64;
        if (wid < 4) {
            const int head = kvh * 4 + wid;
            const float* qptr = Q + (size_t)b * HID + head * DD + h * 64;
            const int arow = wid * 16 + i;
            float dot = 0.f, qn2 = 0.f;
            #pragma unroll
            for (int c = 0; c < 8; c++) {
                float4 qa = __ldg(reinterpret_cast<const float4*>(qptr + c * 8));
                float4 qb = __ldg(reinterpret_cast<const float4*>(qptr + c * 8 + 4));
                float4 ka = __ldg(reinterpret_cast<const float4*>(kptr + c * 8));
                float4 kb = __ldg(reinterpret_cast<const float4*>(kptr + c * 8 + 4));
                dot += qa.x * ka.x + qa.y * ka.y + qa.z * ka.z + qa.w * ka.w +
                       qb.x * kb.x + qb.y * kb.y + qb.z * kb.z + qb.w * kb.w;
                qn2 += qa.x * qa.x + qa.y * qa.y + qa.z * qa.z + qa.w * qa.w +
                       qb.x * qb.x + qb.y * qb.y + qb.z * qb.z + qb.w * qb.w;
                uint4 u = make_uint4(
                    pack_h2(__float2half(qa.x), __float2half(qa.y)),
                    pack_h2(__float2half(qa.z), __float2half(qa.w)),
                    pack_h2(__float2half(qb.x), __float2half(qb.y)),
                    pack_h2(__float2half(qb.z), __float2half(qb.w)));
                uint32_t off = T_A_OFF + h * T_A_PLANE +
                               sw128(arow * 128 + c * 16);
                *reinterpret_cast<uint4*>(ts + off) = u;
            }
            dot += __shfl_xor_sync(0xffffffffu, dot, 1);
            qn2 += __shfl_xor_sync(0xffffffffu, qn2, 1);
            if (h == 0) {
                out[(size_t)b * HH + head] = dot * inv;
                snorm[arow] = qn2;
            }
        } else {
            const int arow = 64 + i;
            float kn2 = 0.f;
            #pragma unroll
            for (int c = 0; c < 8; c++) {
                float4 ka = __ldg(reinterpret_cast<const float4*>(kptr + c * 8));
                float4 kb = __ldg(reinterpret_cast<const float4*>(kptr + c * 8 + 4));
                kn2 += ka.x * ka.x + ka.y * ka.y + ka.z * ka.z + ka.w * ka.w +
                       kb.x * kb.x + kb.y * kb.y + kb.z * kb.z + kb.w * kb.w;
                uint4 u = make_uint4(
                    pack_h2(__float2half(ka.x), __float2half(ka.y)),
                    pack_h2(__float2half(ka.z), __float2half(ka.w)),
                    pack_h2(__float2half(kb.x), __float2half(kb.y)),
                    pack_h2(__float2half(kb.z), __float2half(kb.w)));
                uint32_t off = T_A_OFF + h * T_A_PLANE +
                               sw128(arow * 128 + c * 16);
                *reinterpret_cast<uint4*>(ts + off) = u;
            }
            kn2 += __shfl_xor_sync(0xffffffffu, kn2, 1);
            if (h == 0) snorm[arow] = kn2;
        }
    }
    __syncthreads();

    // ---- hash GEMM: each warp m16(n=128 r)(k=128 d) ----
    {
        const int bi = lane >> 3;
        const int rr = lane & 7;
        const uint32_t a_row = wid * 16 + (bi & 1) * 8 + rr;
        const uint32_t a_col = (bi >> 1) * 16;
        const uint32_t b_rowb = (bi >> 1) * 8 + rr;
        const uint32_t b_col = (bi & 1) * 16;

        float acc[16][4];
        #pragma unroll
        for (int n = 0; n < 16; n++)
            #pragma unroll
            for (int e = 0; e < 4; e++) acc[n][e] = 0.f;

        #pragma unroll
        for (int kp = 0; kp < 8; kp++) {
            const int pl = kp >> 2;
            const int kb = (kp & 3) * 32;
            uint32_t afr[4];
            LDSM4(afr, sbase + T_A_OFF + pl * T_A_PLANE +
                       sw128(a_row * 128 + kb + a_col));
            #pragma unroll
            for (int nt = 0; nt < 8; nt++) {
                uint32_t r4[4];
                LDSM4(r4, sbase + T_HW_OFF + pl * T_HW_PLANE +
                          sw128((nt * 16 + b_rowb) * 128 + kb + b_col));
                uint32_t bf0[2] = {r4[0], r4[1]};
                uint32_t bf1[2] = {r4[2], r4[3]};
                mma16816(acc[nt * 2], afr, bf0);
                mma16816(acc[nt * 2 + 1], afr, bf1);
            }
        }

        // tanh -> codes smem
        const int gr  = lane >> 2;
        const int gc2 = (lane & 3) * 2;
        #pragma unroll
        for (int n = 0; n < 16; n++) {
            #pragma unroll
            for (int e = 0; e < 4; e++) {
                int row = wid * 16 + gr + (e >> 1) * 8;
                int col = n * 8 + gc2 + (e & 1);
                codes[row * T_CODE_STR + col] =
                    0.5f * (tanh_fast(acc[n][e]) + 1.0f);
            }
        }
    }
    __syncthreads();

    // ---- ham reduction: threads 0..127, pair (qrow, half) ----
    if (tid < 128) {
        const int qrow = tid >> 1;
        const int h = tid & 1;
        const int krow = 64 + (qrow & 15);
        const float* qc = &codes[qrow * T_CODE_STR + h * 64];
        const float* kc = &codes[krow * T_CODE_STR + h * 64];
        float s = 0.f;
        #pragma unroll 8
        for (int j = 0; j < 64; j++) s += fabsf(qc[j] - kc[j]);
        s += __shfl_xor_sync(0xffffffffu, s, 1);
        if (h == 0) {
            const int i = qrow & 15;
            const int g = qrow >> 4;
            const int b = b0 + i;
            const float qn = sqrtf(snorm[qrow]);
            const float kn = sqrtf(snorm[64 + i]);
            out[(size_t)BB * HH + (size_t)b * HH + kvh * 4 + g] =
                (1.0f - 2.0f * s / (float)RBIT) * qn * kn * inv;
        }
    }
}

// ---------------------------------------------------------------------------
extern "C" void kernel_launch(void* const* d_in, const int* in_sizes, int n_in,
                              void* d_out, int out_size)
{
    const float* q_hidden = (const float*)d_in[0];
    const float* k_hidden = (const float*)d_in[1];
    const float* q_w      = (const float*)d_in[2];
    const float* q_b      = (const float*)d_in[3];
    const float* k_w      = (const float*)d_in[4];
    const float* k_b      = (const float*)d_in[5];
    const float* hash_w   = (const float*)d_in[6];
    float* out = (float*)d_out;

    void *aq, *ak, *wq, *wk, *qp, *kp, *hwp;
    cudaGetSymbolAddress(&aq, g_Aq);
    cudaGetSymbolAddress(&ak, g_Ak);
    cudaGetSymbolAddress(&wq, g_Wq);
    cudaGetSymbolAddress(&wk, g_Wk);
    cudaGetSymbolAddress(&qp, g_Q);
    cudaGetSymbolAddress(&kp, g_K);
    cudaGetSymbolAddress(&hwp, g_hwT);

    cudaFuncSetAttribute(gemm_mma_kernel,
                         cudaFuncAttributeMaxDynamicSharedMemorySize, GEMM_SMEM);
    cudaFuncSetAttribute(tail_mma_kernel,
                         cudaFuncAttributeMaxDynamicSharedMemorySize, TAIL_SMEM);

    // 1) conversions
    const size_t n4 = (size_t)BB * HID / 4;
    split_hl_kernel<<<(unsigned)(n4 / 256), 256>>>((const float4*)q_hidden, (uint2*)aq, n4);
    split_hl_kernel<<<(unsigned)(n4 / 256), 256>>>((const float4*)k_hidden, (uint2*)ak, n4);
    split_w_kernel<<<dim3(HID / 32, HID / 32), 256>>>(q_w, (__half*)wq, HID);
    split_w_kernel<<<dim3(KOUT / 32, HID / 32), 256>>>(k_w, (__half*)wk, KOUT);
    hw16_kernel<<<64, 256>>>(hash_w, (__half*)hwp);

    // 2) HMMA GEMMs (fp16 split, 2 logical passes)
    gemm_mma_kernel<<<dim3(HID / BN, BB / BM), 256, GEMM_SMEM>>>(
        (const __half*)aq, (const __half*)wq, q_b, (float*)qp, HID);
    gemm_mma_kernel<<<dim3(KOUT / BN, BB / BM), 256, GEMM_SMEM>>>(
        (const __half*)ak, (const __half*)wk, k_b, (float*)kp, KOUT);

    // 3) HMMA tail: scores + hash + ham
    tail_mma_kernel<<<(BB / 16) * KVH, 160, TAIL_SMEM>>>(
        (const float*)qp, (const float*)kp, (const __half*)hwp, out);
}

// round 8
// speedup vs baseline: 8.3580x; 1.7588x over previous
#include <cuda_runtime.h>
#include <cuda_fp16.h>
#include <math.h>
#include <stdint.h>

// Problem constants
#define BB    16384
#define HH    32
#define KVH   8
#define DD    128
#define RBIT  128
#define HID   4096      // H*D
#define KOUT  1024      // KVH*D
#define KA    4096      // GEMM K (plain fp16, no split)

// ---------------------------------------------------------------------------
// Device scratch (no allocations allowed)
// ---------------------------------------------------------------------------
__device__ __half g_Aq[(size_t)BB * KA];        // 128 MB
__device__ __half g_Ak[(size_t)BB * KA];        // 128 MB
__device__ __half g_Wq[(size_t)HID * KA];       // 32 MB  [N,K] layout
__device__ __half g_Wk[(size_t)KOUT * KA];      // 8 MB   [N,K] layout
__device__ float g_Q[(size_t)BB * HID];         // 256 MB
__device__ float g_K[(size_t)BB * KOUT];        // 64 MB
__device__ __half g_hwT[RBIT * DD];             // 32 KB  hash_w^T [r][d] fp16

// ---------------------------------------------------------------------------
// Helpers
// ---------------------------------------------------------------------------
__device__ __forceinline__ uint32_t smem_u32(const void* p) {
    uint32_t a;
    asm("{ .reg .u64 t; cvta.to.shared.u64 t, %1; cvt.u32.u64 %0, t; }"
        : "=r"(a) : "l"(p));
    return a;
}
__device__ __forceinline__ uint32_t sw128(uint32_t off) {
    return off ^ ((off >> 3) & 0x70);   // Swizzle<3,4,3>
}
__device__ __forceinline__ float tanh_fast(float x) {
    float r;
    asm("tanh.approx.f32 %0, %1;" : "=f"(r) : "f"(x));
    return r;
}

#define CP16(dst, src) \
    asm volatile("cp.async.cg.shared.global [%0], [%1], 16;" \
                 :: "r"(dst), "l"(src) : "memory")
#define CP_COMMIT() asm volatile("cp.async.commit_group;" ::: "memory")
#define CP_WAIT(n)  asm volatile("cp.async.wait_group %0;" :: "n"(n) : "memory")

#define LDSM4(r, addr) \
    asm volatile("ldmatrix.sync.aligned.m8n8.x4.shared.b16 {%0,%1,%2,%3}, [%4];" \
                 : "=r"((r)[0]), "=r"((r)[1]), "=r"((r)[2]), "=r"((r)[3]) \
                 : "r"(addr))

__device__ __forceinline__ void mma16816(float* d, const uint32_t* a,
                                         const uint32_t* b) {
    asm volatile(
        "mma.sync.aligned.m16n8k16.row.col.f32.f16.f16.f32 "
        "{%0,%1,%2,%3}, {%4,%5,%6,%7}, {%8,%9}, {%0,%1,%2,%3};"
        : "+f"(d[0]), "+f"(d[1]), "+f"(d[2]), "+f"(d[3])
        : "r"(a[0]), "r"(a[1]), "r"(a[2]), "r"(a[3]), "r"(b[0]), "r"(b[1]));
}

__device__ __forceinline__ uint32_t pack_h2(__half a, __half b) {
    __half2 t = __halves2half2(a, b);
    return *reinterpret_cast<uint32_t*>(&t);
}

// ---------------------------------------------------------------------------
// Conversion: fp32 [rows, 4096] -> fp16 [rows, 4096]
// ---------------------------------------------------------------------------
__global__ __launch_bounds__(256) void tofp16_kernel(
    const float4* __restrict__ X, uint2* __restrict__ Y, size_t n4)
{
    size_t i = (size_t)blockIdx.x * 256 + threadIdx.x;
    if (i >= n4) return;
    float4 v = X[i];
    Y[i] = make_uint2(pack_h2(__float2half(v.x), __float2half(v.y)),
                      pack_h2(__float2half(v.z), __float2half(v.w)));
}

// ---------------------------------------------------------------------------
// Conversion + transpose: W fp32 [4096, N] -> Wt fp16 [N, 4096]
// ---------------------------------------------------------------------------
__global__ __launch_bounds__(256) void split_w_kernel(
    const float* __restrict__ W, __half* __restrict__ Wt, int N)
{
    __shared__ float t[32][33];
    int n0 = blockIdx.x * 32, k0 = blockIdx.y * 32;
    int tx = threadIdx.x & 31, ty = threadIdx.x >> 5;
    #pragma unroll
    for (int i = 0; i < 4; i++)
        t[ty + i * 8][tx] = W[(size_t)(k0 + ty + i * 8) * N + n0 + tx];
    __syncthreads();
    #pragma unroll
    for (int i = 0; i < 4; i++) {
        int n = n0 + ty + i * 8;
        int k = k0 + tx;
        Wt[(size_t)n * KA + k] = __float2half(t[tx][ty + i * 8]);
    }
}

// ---------------------------------------------------------------------------
// hash_w fp32 [d=128][r=128] -> hwT fp16 [r][d]
// ---------------------------------------------------------------------------
__global__ __launch_bounds__(256) void hw16_kernel(
    const float* __restrict__ hw, __half* __restrict__ hwT)
{
    int t = blockIdx.x * 256 + threadIdx.x;     // 16384 total
    int d = t >> 7, r = t & 127;
    hwT[r * DD + d] = __float2half(hw[d * RBIT + r]);
}

// ---------------------------------------------------------------------------
// HMMA GEMM: C[M,N] = A[M,K] @ W[N,K]^T + bias (plain fp16, K=4096)
// BM=BN=128, BK=64, 3-stage cp.async pipeline, 256 threads, 2 CTAs/SM
// ---------------------------------------------------------------------------
#define BM 128
#define BN 128
#define BKK 64
#define STAGES 3
#define ASTG (BM * BKK * 2)                // 16384 bytes per stage
#define GEMM_SMEM (2 * STAGES * ASTG)      // 98304
#define NIT (KA / BKK)                     // 64

__global__ __launch_bounds__(256, 2) void gemm_mma_kernel(
    const __half* __restrict__ A, const __half* __restrict__ W,
    const float* __restrict__ bias, float* __restrict__ C, int N)
{
    extern __shared__ char smem[];
    const uint32_t sA = smem_u32(smem);
    const uint32_t sB = sA + STAGES * ASTG;

    const int tid  = threadIdx.x;
    const int lane = tid & 31;
    const int wid  = tid >> 5;
    const int bm = blockIdx.y * BM;
    const int bn = blockIdx.x * BN;
    const int wm = (wid & 1) * 64;
    const int wn = (wid >> 1) * 32;

    const int lr = tid >> 3;
    const int lc = tid & 7;
    const __half* Ab = A + (size_t)(bm + lr) * KA + lc * 8;
    const __half* Wb = W + (size_t)(bn + lr) * KA + lc * 8;
    const uint32_t sdst = sw128(lr * 128 + lc * 16);

    float acc[4][4][4];
    #pragma unroll
    for (int mt = 0; mt < 4; mt++)
        #pragma unroll
        for (int nt = 0; nt < 4; nt++)
            #pragma unroll
            for (int e = 0; e < 4; e++) acc[mt][nt][e] = 0.f;

    const int bi = lane >> 3;
    const int rr = lane & 7;
    const uint32_t a_row = wm + (bi & 1) * 8 + rr;
    const uint32_t a_col = (bi >> 1) * 16;
    const uint32_t b_row = wn + (bi >> 1) * 8 + rr;
    const uint32_t b_col = (bi & 1) * 16;

    auto load_tile = [&](int stg, int tile) {
        const int k0 = tile * BKK;
        const uint32_t da = sA + stg * ASTG + sdst;
        const uint32_t db = sB + stg * ASTG + sdst;
        #pragma unroll
        for (int i = 0; i < 4; i++) {
            CP16(da + i * 32 * 128, Ab + (size_t)i * 32 * KA + k0);
            CP16(db + i * 32 * 128, Wb + (size_t)i * 32 * KA + k0);
        }
    };

    #pragma unroll
    for (int s = 0; s < STAGES - 1; s++) {
        load_tile(s, s);
        CP_COMMIT();
    }

    int stg = 0;
    #pragma unroll 1
    for (int i = 0; i < NIT; i++) {
        CP_WAIT(STAGES - 2);
        __syncthreads();

        const int nxt = i + STAGES - 1;
        int nstg = stg + STAGES - 1;
        if (nstg >= STAGES) nstg -= STAGES;
        if (nxt < NIT) load_tile(nstg, nxt);
        CP_COMMIT();

        const uint32_t abase = sA + stg * ASTG;
        const uint32_t bbase = sB + stg * ASTG;

        #pragma unroll
        for (int kp = 0; kp < 4; kp++) {
            uint32_t afr[4][4];
            #pragma unroll
            for (int mt = 0; mt < 4; mt++) {
                uint32_t ad = abase +
                    sw128((a_row + mt * 16) * 128 + kp * 32 + a_col);
                LDSM4(afr[mt], ad);
            }
            uint32_t bfr[4][2];
            #pragma unroll
            for (int p = 0; p < 2; p++) {
                uint32_t r4[4];
                uint32_t bd = bbase +
                    sw128((b_row + p * 16) * 128 + kp * 32 + b_col);
                LDSM4(r4, bd);
                bfr[p * 2][0]     = r4[0];
                bfr[p * 2][1]     = r4[1];
                bfr[p * 2 + 1][0] = r4[2];
                bfr[p * 2 + 1][1] = r4[3];
            }
            #pragma unroll
            for (int mt = 0; mt < 4; mt++)
                #pragma unroll
                for (int nt = 0; nt < 4; nt++)
                    mma16816(acc[mt][nt], afr[mt], bfr[nt]);
        }
        if (++stg == STAGES) stg = 0;
    }

    const int gr  = lane >> 2;
    const int gc2 = (lane & 3) * 2;
    #pragma unroll
    for (int mt = 0; mt < 4; mt++) {
        const int r0 = bm + wm + mt * 16 + gr;
        #pragma unroll
        for (int nt = 0; nt < 4; nt++) {
            const int col = bn + wn + nt * 8 + gc2;
            const float2 bv = *reinterpret_cast<const float2*>(&bias[col]);
            float2 o0 = make_float2(acc[mt][nt][0] + bv.x, acc[mt][nt][1] + bv.y);
            float2 o1 = make_float2(acc[mt][nt][2] + bv.x, acc[mt][nt][3] + bv.y);
            *reinterpret_cast<float2*>(&C[(size_t)r0 * N + col]) = o0;
            *reinterpret_cast<float2*>(&C[(size_t)(r0 + 8) * N + col]) = o1;
        }
    }
}

// ---------------------------------------------------------------------------
// HMMA tail: one block per (16 b-rows, kvh). 5 warps (160 threads).
// ---------------------------------------------------------------------------
#define T_A_OFF    0                        // 2 planes of [80][64] fp16
#define T_A_PLANE  10240
#define T_HW_OFF   20480                    // 2 planes of [128][64] fp16
#define T_HW_PLANE 16384
#define T_CODE_OFF 53248                    // [80][132] fp32
#define T_CODE_STR 132
#define T_SN_OFF   (T_CODE_OFF + 80 * T_CODE_STR * 4)   // [80] fp32
#define TAIL_SMEM  (T_SN_OFF + 320 + 64)

__global__ __launch_bounds__(160, 2) void tail_mma_kernel(
    const float* __restrict__ Q, const float* __restrict__ Kp,
    const __half* __restrict__ hwT, float* __restrict__ out)
{
    extern __shared__ char ts[];
    const uint32_t sbase = smem_u32(ts);
    float* codes = reinterpret_cast<float*>(ts + T_CODE_OFF);
    float* snorm = reinterpret_cast<float*>(ts + T_SN_OFF);

    const int tid  = threadIdx.x;
    const int lane = tid & 31;
    const int wid  = tid >> 5;
    const int b0   = (blockIdx.x >> 3) * 16;
    const int kvh  = blockIdx.x & 7;
    const float inv = 0.08838834764831845f;    // 1/sqrt(128)

    for (int c = tid; c < 2048; c += 160) {
        int row = c >> 4, seg = c & 15;
        int pl = seg >> 3;
        uint4 v = *reinterpret_cast<const uint4*>(
            hwT + (size_t)row * DD + pl * 64 + (seg & 7) * 8);
        uint32_t off = T_HW_OFF + pl * T_HW_PLANE +
                       sw128(row * 128 + (seg & 7) * 16);
        *reinterpret_cast<uint4*>(ts + off) = v;
    }

    {
        const int i = lane >> 1;
        const int h = lane & 1;
        const int b = b0 + i;
        const float* kptr = Kp + (size_t)b * KOUT + kvh * DD + h * 64;
        if (wid < 4) {
            const int head = kvh * 4 + wid;
            const float* qptr = Q + (size_t)b * HID + head * DD + h * 64;
            const int arow = wid * 16 + i;
            float dot = 0.f, qn2 = 0.f;
            #pragma unroll
            for (int c = 0; c < 8; c++) {
                float4 qa = __ldg(reinterpret_cast<const float4*>(qptr + c * 8));
                float4 qb = __ldg(reinterpret_cast<const float4*>(qptr + c * 8 + 4));
                float4 ka = __ldg(reinterpret_cast<const float4*>(kptr + c * 8));
                float4 kb = __ldg(reinterpret_cast<const float4*>(kptr + c * 8 + 4));
                dot += qa.x * ka.x + qa.y * ka.y + qa.z * ka.z + qa.w * ka.w +
                       qb.x * kb.x + qb.y * kb.y + qb.z * kb.z + qb.w * kb.w;
                qn2 += qa.x * qa.x + qa.y * qa.y + qa.z * qa.z + qa.w * qa.w +
                       qb.x * qb.x + qb.y * qb.y + qb.z * qb.z + qb.w * qb.w;
                uint4 u = make_uint4(
                    pack_h2(__float2half(qa.x), __float2half(qa.y)),
                    pack_h2(__float2half(qa.z), __float2half(qa.w)),
                    pack_h2(__float2half(qb.x), __float2half(qb.y)),
                    pack_h2(__float2half(qb.z), __float2half(qb.w)));
                uint32_t off = T_A_OFF + h * T_A_PLANE +
                               sw128(arow * 128 + c * 16);
                *reinterpret_cast<uint4*>(ts + off) = u;
            }
            dot += __shfl_xor_sync(0xffffffffu, dot, 1);
            qn2 += __shfl_xor_sync(0xffffffffu, qn2, 1);
            if (h == 0) {
                out[(size_t)b * HH + head] = dot * inv;
                snorm[arow] = qn2;
            }
        } else {
            const int arow = 64 + i;
            float kn2 = 0.f;
            #pragma unroll
            for (int c = 0; c < 8; c++) {
                float4 ka = __ldg(reinterpret_cast<const float4*>(kptr + c * 8));
                float4 kb = __ldg(reinterpret_cast<const float4*>(kptr + c * 8 + 4));
                kn2 += ka.x * ka.x + ka.y * ka.y + ka.z * ka.z + ka.w * ka.w +
                       kb.x * kb.x + kb.y * kb.y + kb.z * kb.z + kb.w * kb.w;
                uint4 u = make_uint4(
                    pack_h2(__float2half(ka.x), __float2half(ka.y)),
                    pack_h2(__float2half(ka.z), __float2half(ka.w)),
                    pack_h2(__float2half(kb.x), __float2half(kb.y)),
                    pack_h2(__float2half(kb.z), __float2half(kb.w)));
                uint32_t off = T_A_OFF + h * T_A_PLANE +
                               sw128(arow * 128 + c * 16);
                *reinterpret_cast<uint4*>(ts + off) = u;
            }
            kn2 += __shfl_xor_sync(0xffffffffu, kn2, 1);
            if (h == 0) snorm[arow] = kn2;
        }
    }
    __syncthreads();

    {
        const int bi = lane >> 3;
        const int rr = lane & 7;
        const uint32_t a_row = wid * 16 + (bi & 1) * 8 + rr;
        const uint32_t a_col = (bi >> 1) * 16;
        const uint32_t b_rowb = (bi >> 1) * 8 + rr;
        const uint32_t b_col = (bi & 1) * 16;

        float acc[16][4];
        #pragma unroll
        for (int n = 0; n < 16; n++)
            #pragma unroll
            for (int e = 0; e < 4; e++) acc[n][e] = 0.f;

        #pragma unroll
        for (int kp = 0; kp < 8; kp++) {
            const int pl = kp >> 2;
            const int kb = (kp & 3) * 32;
            uint32_t afr[4];
            LDSM4(afr, sbase + T_A_OFF + pl * T_A_PLANE +
                       sw128(a_row * 128 + kb + a_col));
            #pragma unroll
            for (int nt = 0; nt < 8; nt++) {
                uint32_t r4[4];
                LDSM4(r4, sbase + T_HW_OFF + pl * T_HW_PLANE +
                          sw128((nt * 16 + b_rowb) * 128 + kb + b_col));
                uint32_t bf0[2] = {r4[0], r4[1]};
                uint32_t bf1[2] = {r4[2], r4[3]};
                mma16816(acc[nt * 2], afr, bf0);
                mma16816(acc[nt * 2 + 1], afr, bf1);
            }
        }

        const int gr  = lane >> 2;
        const int gc2 = (lane & 3) * 2;
        #pragma unroll
        for (int n = 0; n < 16; n++) {
            #pragma unroll
            for (int e = 0; e < 4; e++) {
                int row = wid * 16 + gr + (e >> 1) * 8;
                int col = n * 8 + gc2 + (e & 1);
                codes[row * T_CODE_STR + col] =
                    0.5f * (tanh_fast(acc[n][e]) + 1.0f);
            }
        }
    }
    __syncthreads();

    if (tid < 128) {
        const int qrow = tid >> 1;
        const int h = tid & 1;
        const int krow = 64 + (qrow & 15);
        const float* qc = &codes[qrow * T_CODE_STR + h * 64];
        const float* kc = &codes[krow * T_CODE_STR + h * 64];
        float s = 0.f;
        #pragma unroll 8
        for (int j = 0; j < 64; j++) s += fabsf(qc[j] - kc[j]);
        s += __shfl_xor_sync(0xffffffffu, s, 1);
        if (h == 0) {
            const int i = qrow & 15;
            const int g = qrow >> 4;
            const int b = b0 + i;
            const float qn = sqrtf(snorm[qrow]);
            const float kn = sqrtf(snorm[64 + i]);
            out[(size_t)BB * HH + (size_t)b * HH + kvh * 4 + g] =
                (1.0f - 2.0f * s / (float)RBIT) * qn * kn * inv;
        }
    }
}

// ---------------------------------------------------------------------------
extern "C" void kernel_launch(void* const* d_in, const int* in_sizes, int n_in,
                              void* d_out, int out_size)
{
    const float* q_hidden = (const float*)d_in[0];
    const float* k_hidden = (const float*)d_in[1];
    const float* q_w      = (const float*)d_in[2];
    const float* q_b      = (const float*)d_in[3];
    const float* k_w      = (const float*)d_in[4];
    const float* k_b      = (const float*)d_in[5];
    const float* hash_w   = (const float*)d_in[6];
    float* out = (float*)d_out;

    void *aq, *ak, *wq, *wk, *qp, *kp, *hwp;
    cudaGetSymbolAddress(&aq, g_Aq);
    cudaGetSymbolAddress(&ak, g_Ak);
    cudaGetSymbolAddress(&wq, g_Wq);
    cudaGetSymbolAddress(&wk, g_Wk);
    cudaGetSymbolAddress(&qp, g_Q);
    cudaGetSymbolAddress(&kp, g_K);
    cudaGetSymbolAddress(&hwp, g_hwT);

    cudaFuncSetAttribute(gemm_mma_kernel,
                         cudaFuncAttributeMaxDynamicSharedMemorySize, GEMM_SMEM);
    cudaFuncSetAttribute(tail_mma_kernel,
                         cudaFuncAttributeMaxDynamicSharedMemorySize, TAIL_SMEM);

    // 1) conversions
    const size_t n4 = (size_t)BB * HID / 4;
    tofp16_kernel<<<(unsigned)(n4 / 256), 256>>>((const float4*)q_hidden, (uint2*)aq, n4);
    tofp16_kernel<<<(unsigned)(n4 / 256), 256>>>((const float4*)k_hidden, (uint2*)ak, n4);
    split_w_kernel<<<dim3(HID / 32, HID / 32), 256>>>(q_w, (__half*)wq, HID);
    split_w_kernel<<<dim3(KOUT / 32, HID / 32), 256>>>(k_w, (__half*)wk, KOUT);
    hw16_kernel<<<64, 256>>>(hash_w, (__half*)hwp);

    // 2) HMMA GEMMs (plain fp16, K=4096)
    gemm_mma_kernel<<<dim3(HID / BN, BB / BM), 256, GEMM_SMEM>>>(
        (const __half*)aq, (const __half*)wq, q_b, (float*)qp, HID);
    gemm_mma_kernel<<<dim3(KOUT / BN, BB / BM), 256, GEMM_SMEM>>>(
        (const __half*)ak, (const __half*)wk, k_b, (float*)kp, KOUT);

    // 3) HMMA tail: scores + hash + ham
    tail_mma_kernel<<<(BB / 16) * KVH, 160, TAIL_SMEM>>>(
        (const float*)qp, (const float*)kp, (const __half*)hwp, out);
}

// round 9
// speedup vs baseline: 8.4877x; 1.0155x over previous
#include <cuda_runtime.h>
#include <cuda_fp16.h>
#include <math.h>
#include <stdint.h>

// Problem constants
#define BB    16384
#define HH    32
#define KVH   8
#define DD    128
#define RBIT  128
#define HID   4096      // H*D
#define KOUT  1024      // KVH*D
#define KA    4096      // GEMM K (plain fp16)

// ---------------------------------------------------------------------------
// Device scratch (no allocations allowed)
// ---------------------------------------------------------------------------
__device__ __half g_Aq[(size_t)BB * KA];        // 128 MB
__device__ __half g_Ak[(size_t)BB * KA];        // 128 MB
__device__ __half g_Wq[(size_t)HID * KA];       // 32 MB  [N,K] layout
__device__ __half g_Wk[(size_t)KOUT * KA];      // 8 MB   [N,K] layout
__device__ float g_Q[(size_t)BB * HID];         // 256 MB
__device__ float g_K[(size_t)BB * KOUT];        // 64 MB
__device__ __half g_hwT[RBIT * DD];             // 32 KB  hash_w^T [r][d] fp16

// ---------------------------------------------------------------------------
// Helpers
// ---------------------------------------------------------------------------
__device__ __forceinline__ uint32_t smem_u32(const void* p) {
    uint32_t a;
    asm("{ .reg .u64 t; cvta.to.shared.u64 t, %1; cvt.u32.u64 %0, t; }"
        : "=r"(a) : "l"(p));
    return a;
}
__device__ __forceinline__ uint32_t sw128(uint32_t off) {
    return off ^ ((off >> 3) & 0x70);   // Swizzle<3,4,3>
}
__device__ __forceinline__ float tanh_fast(float x) {
    float r;
    asm("tanh.approx.f32 %0, %1;" : "=f"(r) : "f"(x));
    return r;
}

#define CP16(dst, src) \
    asm volatile("cp.async.cg.shared.global [%0], [%1], 16;" \
                 :: "r"(dst), "l"(src) : "memory")
#define CP_COMMIT() asm volatile("cp.async.commit_group;" ::: "memory")
#define CP_WAIT(n)  asm volatile("cp.async.wait_group %0;" :: "n"(n) : "memory")

#define LDSM4(r, addr) \
    asm volatile("ldmatrix.sync.aligned.m8n8.x4.shared.b16 {%0,%1,%2,%3}, [%4];" \
                 : "=r"((r)[0]), "=r"((r)[1]), "=r"((r)[2]), "=r"((r)[3]) \
                 : "r"(addr))

__device__ __forceinline__ void mma16816(float* d, const uint32_t* a,
                                         const uint32_t* b) {
    asm volatile(
        "mma.sync.aligned.m16n8k16.row.col.f32.f16.f16.f32 "
        "{%0,%1,%2,%3}, {%4,%5,%6,%7}, {%8,%9}, {%0,%1,%2,%3};"
        : "+f"(d[0]), "+f"(d[1]), "+f"(d[2]), "+f"(d[3])
        : "r"(a[0]), "r"(a[1]), "r"(a[2]), "r"(a[3]), "r"(b[0]), "r"(b[1]));
}

__device__ __forceinline__ uint32_t pack_h2(__half a, __half b) {
    __half2 t = __halves2half2(a, b);
    return *reinterpret_cast<uint32_t*>(&t);
}

// ---------------------------------------------------------------------------
// Conversion: fp32 [rows, 4096] -> fp16 [rows, 4096]
// ---------------------------------------------------------------------------
__global__ __launch_bounds__(256) void tofp16_kernel(
    const float4* __restrict__ X, uint2* __restrict__ Y, size_t n4)
{
    size_t i = (size_t)blockIdx.x * 256 + threadIdx.x;
    if (i >= n4) return;
    float4 v = X[i];
    Y[i] = make_uint2(pack_h2(__float2half(v.x), __float2half(v.y)),
                      pack_h2(__float2half(v.z), __float2half(v.w)));
}

// ---------------------------------------------------------------------------
// Conversion + transpose: W fp32 [4096, N] -> Wt fp16 [N, 4096]
// ---------------------------------------------------------------------------
__global__ __launch_bounds__(256) void split_w_kernel(
    const float* __restrict__ W, __half* __restrict__ Wt, int N)
{
    __shared__ float t[32][33];
    int n0 = blockIdx.x * 32, k0 = blockIdx.y * 32;
    int tx = threadIdx.x & 31, ty = threadIdx.x >> 5;
    #pragma unroll
    for (int i = 0; i < 4; i++)
        t[ty + i * 8][tx] = W[(size_t)(k0 + ty + i * 8) * N + n0 + tx];
    __syncthreads();
    #pragma unroll
    for (int i = 0; i < 4; i++) {
        int n = n0 + ty + i * 8;
        int k = k0 + tx;
        Wt[(size_t)n * KA + k] = __float2half(t[tx][ty + i * 8]);
    }
}

// ---------------------------------------------------------------------------
// hash_w fp32 [d=128][r=128] -> hwT fp16 [r][d]
// ---------------------------------------------------------------------------
__global__ __launch_bounds__(256) void hw16_kernel(
    const float* __restrict__ hw, __half* __restrict__ hwT)
{
    int t = blockIdx.x * 256 + threadIdx.x;     // 16384 total
    int d = t >> 7, r = t & 127;
    hwT[r * DD + d] = __float2half(hw[d * RBIT + r]);
}

// ---------------------------------------------------------------------------
// HMMA GEMM: C[M,N] = A[M,K] @ W[N,K]^T + bias (plain fp16, K=4096)
// BM=BN=128, BK=64, 3-stage cp.async pipeline, 256 threads, 2 CTAs/SM
// ---------------------------------------------------------------------------
#define BM 128
#define BN 128
#define BKK 64
#define STAGES 3
#define ASTG (BM * BKK * 2)                // 16384 bytes per stage
#define GEMM_SMEM (2 * STAGES * ASTG)      // 98304
#define NIT (KA / BKK)                     // 64

__global__ __launch_bounds__(256, 2) void gemm_mma_kernel(
    const __half* __restrict__ A, const __half* __restrict__ W,
    const float* __restrict__ bias, float* __restrict__ C, int N)
{
    extern __shared__ char smem[];
    const uint32_t sA = smem_u32(smem);
    const uint32_t sB = sA + STAGES * ASTG;

    const int tid  = threadIdx.x;
    const int lane = tid & 31;
    const int wid  = tid >> 5;
    const int bm = blockIdx.y * BM;
    const int bn = blockIdx.x * BN;
    const int wm = (wid & 1) * 64;
    const int wn = (wid >> 1) * 32;

    const int lr = tid >> 3;
    const int lc = tid & 7;
    const __half* Ab = A + (size_t)(bm + lr) * KA + lc * 8;
    const __half* Wb = W + (size_t)(bn + lr) * KA + lc * 8;
    const uint32_t sdst = sw128(lr * 128 + lc * 16);

    float acc[4][4][4];
    #pragma unroll
    for (int mt = 0; mt < 4; mt++)
        #pragma unroll
        for (int nt = 0; nt < 4; nt++)
            #pragma unroll
            for (int e = 0; e < 4; e++) acc[mt][nt][e] = 0.f;

    const int bi = lane >> 3;
    const int rr = lane & 7;
    const uint32_t a_row = wm + (bi & 1) * 8 + rr;
    const uint32_t a_col = (bi >> 1) * 16;
    const uint32_t b_row = wn + (bi >> 1) * 8 + rr;
    const uint32_t b_col = (bi & 1) * 16;

    auto load_tile = [&](int stg, int tile) {
        const int k0 = tile * BKK;
        const uint32_t da = sA + stg * ASTG + sdst;
        const uint32_t db = sB + stg * ASTG + sdst;
        #pragma unroll
        for (int i = 0; i < 4; i++) {
            CP16(da + i * 32 * 128, Ab + (size_t)i * 32 * KA + k0);
            CP16(db + i * 32 * 128, Wb + (size_t)i * 32 * KA + k0);
        }
    };

    #pragma unroll
    for (int s = 0; s < STAGES - 1; s++) {
        load_tile(s, s);
        CP_COMMIT();
    }

    int stg = 0;
    #pragma unroll 1
    for (int i = 0; i < NIT; i++) {
        CP_WAIT(STAGES - 2);
        __syncthreads();

        const int nxt = i + STAGES - 1;
        int nstg = stg + STAGES - 1;
        if (nstg >= STAGES) nstg -= STAGES;
        if (nxt < NIT) load_tile(nstg, nxt);
        CP_COMMIT();

        const uint32_t abase = sA + stg * ASTG;
        const uint32_t bbase = sB + stg * ASTG;

        #pragma unroll
        for (int kp = 0; kp < 4; kp++) {
            uint32_t afr[4][4];
            #pragma unroll
            for (int mt = 0; mt < 4; mt++) {
                uint32_t ad = abase +
                    sw128((a_row + mt * 16) * 128 + kp * 32 + a_col);
                LDSM4(afr[mt], ad);
            }
            uint32_t bfr[4][2];
            #pragma unroll
            for (int p = 0; p < 2; p++) {
                uint32_t r4[4];
                uint32_t bd = bbase +
                    sw128((b_row + p * 16) * 128 + kp * 32 + b_col);
                LDSM4(r4, bd);
                bfr[p * 2][0]     = r4[0];
                bfr[p * 2][1]     = r4[1];
                bfr[p * 2 + 1][0] = r4[2];
                bfr[p * 2 + 1][1] = r4[3];
            }
            #pragma unroll
            for (int mt = 0; mt < 4; mt++)
                #pragma unroll
                for (int nt = 0; nt < 4; nt++)
                    mma16816(acc[mt][nt], afr[mt], bfr[nt]);
        }
        if (++stg == STAGES) stg = 0;
    }

    const int gr  = lane >> 2;
    const int gc2 = (lane & 3) * 2;
    #pragma unroll
    for (int mt = 0; mt < 4; mt++) {
        const int r0 = bm + wm + mt * 16 + gr;
        #pragma unroll
        for (int nt = 0; nt < 4; nt++) {
            const int col = bn + wn + nt * 8 + gc2;
            const float2 bv = *reinterpret_cast<const float2*>(&bias[col]);
            float2 o0 = make_float2(acc[mt][nt][0] + bv.x, acc[mt][nt][1] + bv.y);
            float2 o1 = make_float2(acc[mt][nt][2] + bv.x, acc[mt][nt][3] + bv.y);
            *reinterpret_cast<float2*>(&C[(size_t)r0 * N + col]) = o0;
            *reinterpret_cast<float2*>(&C[(size_t)(r0 + 8) * N + col]) = o1;
        }
    }
}

// ---------------------------------------------------------------------------
// HMMA tail: one block per (16 b-rows, kvh). 5 warps (160 threads).
// ---------------------------------------------------------------------------
#define T_A_OFF    0                        // 2 planes of [80][64] fp16
#define T_A_PLANE  10240
#define T_HW_OFF   20480                    // 2 planes of [128][64] fp16
#define T_HW_PLANE 16384
#define T_CODE_OFF 53248                    // [80][132] fp32
#define T_CODE_STR 132
#define T_SN_OFF   (T_CODE_OFF + 80 * T_CODE_STR * 4)   // [80] fp32
#define TAIL_SMEM  (T_SN_OFF + 320 + 64)

__global__ __launch_bounds__(160, 2) void tail_mma_kernel(
    const float* __restrict__ Q, const float* __restrict__ Kp,
    const __half* __restrict__ hwT, float* __restrict__ out)
{
    extern __shared__ char ts[];
    const uint32_t sbase = smem_u32(ts);
    float* codes = reinterpret_cast<float*>(ts + T_CODE_OFF);
    float* snorm = reinterpret_cast<float*>(ts + T_SN_OFF);

    const int tid  = threadIdx.x;
    const int lane = tid & 31;
    const int wid  = tid >> 5;
    const int b0   = (blockIdx.x >> 3) * 16;
    const int kvh  = blockIdx.x & 7;
    const float inv = 0.08838834764831845f;    // 1/sqrt(128)

    for (int c = tid; c < 2048; c += 160) {
        int row = c >> 4, seg = c & 15;
        int pl = seg >> 3;
        uint4 v = *reinterpret_cast<const uint4*>(
            hwT + (size_t)row * DD + pl * 64 + (seg & 7) * 8);
        uint32_t off = T_HW_OFF + pl * T_HW_PLANE +
                       sw128(row * 128 + (seg & 7) * 16);
        *reinterpret_cast<uint4*>(ts + off) = v;
    }

    {
        const int i = lane >> 1;
        const int h = lane & 1;
        const int b = b0 + i;
        const float* kptr = Kp + (size_t)b * KOUT + kvh * DD + h * 64;
        if (wid < 4) {
            const int head = kvh * 4 + wid;
            const float* qptr = Q + (size_t)b * HID + head * DD + h * 64;
            const int arow = wid * 16 + i;
            float dot = 0.f, qn2 = 0.f;
            #pragma unroll
            for (int c = 0; c < 8; c++) {
                float4 qa = __ldg(reinterpret_cast<const float4*>(qptr + c * 8));
                float4 qb = __ldg(reinterpret_cast<const float4*>(qptr + c * 8 + 4));
                float4 ka = __ldg(reinterpret_cast<const float4*>(kptr + c * 8));
                float4 kb = __ldg(reinterpret_cast<const float4*>(kptr + c * 8 + 4));
                dot += qa.x * ka.x + qa.y * ka.y + qa.z * ka.z + qa.w * ka.w +
                       qb.x * kb.x + qb.y * kb.y + qb.z * kb.z + qb.w * kb.w;
                qn2 += qa.x * qa.x + qa.y * qa.y + qa.z * qa.z + qa.w * qa.w +
                       qb.x * qb.x + qb.y * qb.y + qb.z * qb.z + qb.w * qb.w;
                uint4 u = make_uint4(
                    pack_h2(__float2half(qa.x), __float2half(qa.y)),
                    pack_h2(__float2half(qa.z), __float2half(qa.w)),
                    pack_h2(__float2half(qb.x), __float2half(qb.y)),
                    pack_h2(__float2half(qb.z), __float2half(qb.w)));
                uint32_t off = T_A_OFF + h * T_A_PLANE +
                               sw128(arow * 128 + c * 16);
                *reinterpret_cast<uint4*>(ts + off) = u;
            }
            dot += __shfl_xor_sync(0xffffffffu, dot, 1);
            qn2 += __shfl_xor_sync(0xffffffffu, qn2, 1);
            if (h == 0) {
                out[(size_t)b * HH + head] = dot * inv;
                snorm[arow] = qn2;
            }
        } else {
            const int arow = 64 + i;
            float kn2 = 0.f;
            #pragma unroll
            for (int c = 0; c < 8; c++) {
                float4 ka = __ldg(reinterpret_cast<const float4*>(kptr + c * 8));
                float4 kb = __ldg(reinterpret_cast<const float4*>(kptr + c * 8 + 4));
                kn2 += ka.x * ka.x + ka.y * ka.y + ka.z * ka.z + ka.w * ka.w +
                       kb.x * kb.x + kb.y * kb.y + kb.z * kb.z + kb.w * kb.w;
                uint4 u = make_uint4(
                    pack_h2(__float2half(ka.x), __float2half(ka.y)),
                    pack_h2(__float2half(ka.z), __float2half(ka.w)),
                    pack_h2(__float2half(kb.x), __float2half(kb.y)),
                    pack_h2(__float2half(kb.z), __float2half(kb.w)));
                uint32_t off = T_A_OFF + h * T_A_PLANE +
                               sw128(arow * 128 + c * 16);
                *reinterpret_cast<uint4*>(ts + off) = u;
            }
            kn2 += __shfl_xor_sync(0xffffffffu, kn2, 1);
            if (h == 0) snorm[arow] = kn2;
        }
    }
    __syncthreads();

    {
        const int bi = lane >> 3;
        const int rr = lane & 7;
        const uint32_t a_row = wid * 16 + (bi & 1) * 8 + rr;
        const uint32_t a_col = (bi >> 1) * 16;
        const uint32_t b_rowb = (bi >> 1) * 8 + rr;
        const uint32_t b_col = (bi & 1) * 16;

        float acc[16][4];
        #pragma unroll
        for (int n = 0; n < 16; n++)
            #pragma unroll
            for (int e = 0; e < 4; e++) acc[n][e] = 0.f;

        #pragma unroll
        for (int kp = 0; kp < 8; kp++) {
            const int pl = kp >> 2;
            const int kb = (kp & 3) * 32;
            uint32_t afr[4];
            LDSM4(afr, sbase + T_A_OFF + pl * T_A_PLANE +
                       sw128(a_row * 128 + kb + a_col));
            #pragma unroll
            for (int nt = 0; nt < 8; nt++) {
                uint32_t r4[4];
                LDSM4(r4, sbase + T_HW_OFF + pl * T_HW_PLANE +
                          sw128((nt * 16 + b_rowb) * 128 + kb + b_col));
                uint32_t bf0[2] = {r4[0], r4[1]};
                uint32_t bf1[2] = {r4[2], r4[3]};
                mma16816(acc[nt * 2], afr, bf0);
                mma16816(acc[nt * 2 + 1], afr, bf1);
            }
        }

        const int gr  = lane >> 2;
        const int gc2 = (lane & 3) * 2;
        #pragma unroll
        for (int n = 0; n < 16; n++) {
            #pragma unroll
            for (int e = 0; e < 4; e++) {
                int row = wid * 16 + gr + (e >> 1) * 8;
                int col = n * 8 + gc2 + (e & 1);
                codes[row * T_CODE_STR + col] =
                    0.5f * (tanh_fast(acc[n][e]) + 1.0f);
            }
        }
    }
    __syncthreads();

    if (tid < 128) {
        const int qrow = tid >> 1;
        const int h = tid & 1;
        const int krow = 64 + (qrow & 15);
        const float* qc = &codes[qrow * T_CODE_STR + h * 64];
        const float* kc = &codes[krow * T_CODE_STR + h * 64];
        float s = 0.f;
        #pragma unroll 8
        for (int j = 0; j < 64; j++) s += fabsf(qc[j] - kc[j]);
        s += __shfl_xor_sync(0xffffffffu, s, 1);
        if (h == 0) {
            const int i = qrow & 15;
            const int g = qrow >> 4;
            const int b = b0 + i;
            const float qn = sqrtf(snorm[qrow]);
            const float kn = sqrtf(snorm[64 + i]);
            out[(size_t)BB * HH + (size_t)b * HH + kvh * 4 + g] =
                (1.0f - 2.0f * s / (float)RBIT) * qn * kn * inv;
        }
    }
}

// ---------------------------------------------------------------------------
// Stream/event resources: created ONCE on the first (uncaptured) correctness
// call; reused on the capture call so no stream/event creation APIs execute
// during graph capture. Captured node topology is identical on every call.
// ---------------------------------------------------------------------------
struct SideStream {
    cudaStream_t s2;
    cudaEvent_t evQ, evJoin;
    SideStream() {
        cudaStreamCreateWithFlags(&s2, cudaStreamNonBlocking);
        cudaEventCreateWithFlags(&evQ, cudaEventDisableTiming);
        cudaEventCreateWithFlags(&evJoin, cudaEventDisableTiming);
    }
};
static SideStream& side() { static SideStream s; return s; }

// ---------------------------------------------------------------------------
extern "C" void kernel_launch(void* const* d_in, const int* in_sizes, int n_in,
                              void* d_out, int out_size)
{
    const float* q_hidden = (const float*)d_in[0];
    const float* k_hidden = (const float*)d_in[1];
    const float* q_w      = (const float*)d_in[2];
    const float* q_b      = (const float*)d_in[3];
    const float* k_w      = (const float*)d_in[4];
    const float* k_b      = (const float*)d_in[5];
    const float* hash_w   = (const float*)d_in[6];
    float* out = (float*)d_out;

    void *aq, *ak, *wq, *wk, *qp, *kp, *hwp;
    cudaGetSymbolAddress(&aq, g_Aq);
    cudaGetSymbolAddress(&ak, g_Ak);
    cudaGetSymbolAddress(&wq, g_Wq);
    cudaGetSymbolAddress(&wk, g_Wk);
    cudaGetSymbolAddress(&qp, g_Q);
    cudaGetSymbolAddress(&kp, g_K);
    cudaGetSymbolAddress(&hwp, g_hwT);

    cudaFuncSetAttribute(gemm_mma_kernel,
                         cudaFuncAttributeMaxDynamicSharedMemorySize, GEMM_SMEM);
    cudaFuncSetAttribute(tail_mma_kernel,
                         cudaFuncAttributeMaxDynamicSharedMemorySize, TAIL_SMEM);

    SideStream& ss = side();
    const size_t n4 = (size_t)BB * HID / 4;

    // ---- stream 0: Q-side pipeline ----
    hw16_kernel<<<64, 256>>>(hash_w, (__half*)hwp);
    split_w_kernel<<<dim3(HID / 32, HID / 32), 256>>>(q_w, (__half*)wq, HID);
    tofp16_kernel<<<(unsigned)(n4 / 256), 256>>>(
        (const float4*)q_hidden, (uint2*)aq, n4);
    cudaEventRecord(ss.evQ, 0);
    gemm_mma_kernel<<<dim3(HID / BN, BB / BM), 256, GEMM_SMEM>>>(
        (const __half*)aq, (const __half*)wq, q_b, (float*)qp, HID);

    // ---- side stream: K-side pipeline, overlapped with gemmQ ----
    cudaStreamWaitEvent(ss.s2, ss.evQ, 0);
    split_w_kernel<<<dim3(KOUT / 32, HID / 32), 256, 0, ss.s2>>>(
        k_w, (__half*)wk, KOUT);
    tofp16_kernel<<<(unsigned)(n4 / 256), 256, 0, ss.s2>>>(
        (const float4*)k_hidden, (uint2*)ak, n4);
    gemm_mma_kernel<<<dim3(KOUT / BN, BB / BM), 256, GEMM_SMEM, ss.s2>>>(
        (const __half*)ak, (const __half*)wk, k_b, (float*)kp, KOUT);
    cudaEventRecord(ss.evJoin, ss.s2);

    // ---- join + tail ----
    cudaStreamWaitEvent(0, ss.evJoin, 0);
    tail_mma_kernel<<<(BB / 16) * KVH, 160, TAIL_SMEM>>>(
        (const float*)qp, (const float*)kp, (const __half*)hwp, out);
}